// round 6
// baseline (speedup 1.0000x reference)
#include <cuda_runtime.h>
#include <float.h>

#define NN 50000
#define EE 800000

// ---------------- scratch (no allocation allowed -> __device__ globals) ----
__device__ float d_feat[(size_t)NN * 256];   // x @ W_fc           [N,H*OUT]
__device__ float d_z[(size_t)NN * 64];       // x @ W_gm + b_gm    [N,MAP]
__device__ float d_el[NN * 4];               // attn_l dot         [N,H]
__device__ float d_er[NN * 4];               // attn_r dot         [N,H]
__device__ float d_gs[NN * 4];               // x @ W_gate[0:128]  [N,H]
__device__ float d_gmn[NN * 4];              // x @ W_gate[192:]   [N,H]
__device__ float d_gated[(size_t)NN * 64];   // gated head-mean    [N,OUT]
__device__ int   d_deg[NN];
__device__ int   d_cur[NN];
__device__ int   d_rowoff[NN + 1];
__device__ int   d_srt[EE];                  // src ids sorted by dst (CSR)
__device__ int   d_bsum[64];
__device__ int   d_bpre[64];

__device__ __forceinline__ float lrelu(float v) { return v > 0.f ? v : 0.2f * v; }

#define PACK2(out, lo, hi) \
    asm("mov.b64 %0, {%1, %2};" : "=l"(out) : "r"(__float_as_uint(lo)), "r"(__float_as_uint(hi)))
#define UNPACK2(lo, hi, in) \
    do { unsigned _ulo, _uhi; \
         asm("mov.b64 {%0, %1}, %2;" : "=r"(_ulo), "=r"(_uhi) : "l"(in)); \
         lo = __uint_as_float(_ulo); hi = __uint_as_float(_uhi); } while (0)
#define FMA2(acc, a, b) \
    asm("fma.rn.f32x2 %0, %1, %2, %0;" : "+l"(acc) : "l"(a), "l"(b))

// ---------------- CSR build ------------------------------------------------
__global__ void k_count(const int* __restrict__ dst) {
    int e = blockIdx.x * blockDim.x + threadIdx.x;
    if (e < EE) atomicAdd(&d_deg[dst[e]], 1);
}

__global__ void k_blocksum() {
    __shared__ int sh[1024];
    int i = blockIdx.x * 1024 + threadIdx.x;
    sh[threadIdx.x] = (i < NN) ? d_deg[i] : 0;
    __syncthreads();
    for (int s = 512; s; s >>= 1) {
        if (threadIdx.x < s) sh[threadIdx.x] += sh[threadIdx.x + s];
        __syncthreads();
    }
    if (threadIdx.x == 0) d_bsum[blockIdx.x] = sh[0];
}

__global__ void k_scanbsum(int nb) {
    __shared__ int sh[64];
    int t = threadIdx.x;
    int v = (t < nb) ? d_bsum[t] : 0;
    sh[t] = v;
    __syncthreads();
    for (int o = 1; o < 64; o <<= 1) {
        int u = (t >= o) ? sh[t - o] : 0;
        __syncthreads();
        sh[t] += u;
        __syncthreads();
    }
    if (t < nb) d_bpre[t] = sh[t] - v;
}

__global__ void k_scanfinal() {
    __shared__ int sh[1024];
    int tid = threadIdx.x;
    int i = blockIdx.x * 1024 + tid;
    int v = (i < NN) ? d_deg[i] : 0;
    sh[tid] = v;
    __syncthreads();
    for (int off = 1; off < 1024; off <<= 1) {
        int t = (tid >= off) ? sh[tid - off] : 0;
        __syncthreads();
        sh[tid] += t;
        __syncthreads();
    }
    if (i < NN) d_rowoff[i] = d_bpre[blockIdx.x] + sh[tid] - v;
    if (i == 0) d_rowoff[NN] = EE;
}

__global__ void k_scatter(const int* __restrict__ src, const int* __restrict__ dst) {
    int e = blockIdx.x * blockDim.x + threadIdx.x;
    if (e < EE) {
        int d = dst[e];
        int p = d_rowoff[d] + atomicAdd(&d_cur[d], 1);
        d_srt[p] = src[e];
    }
}

// ---------------- tiled fp32 GEMM with packed FFMA2, wide microtile --------
// BMxBN block tile, 128 threads, TM=16 x TN=8 micro-tile, BK=16.
// smem demand: 24 floats (96B) per 128 FMA per thread -> under crossbar at FFMA2 rate.
template<int BM, int BN, int TM, int TN>
__global__ void __launch_bounds__((BM / TM) * (BN / TN))
k_gemm(const float* __restrict__ A1, int K1,
       const float* __restrict__ A2, int K2,
       const float* __restrict__ B,
       const float* __restrict__ bias,
       float* __restrict__ C, int M, int Ncols) {
    constexpr int BK = 16;
    constexpr int NTH = (BM / TM) * (BN / TN);   // 128
    __shared__ __align__(16) float As[BK][BM + 4];
    __shared__ __align__(16) float Bs[BK][BN + 4];
    int t = threadIdx.x;
    int tx = t % (BN / TN);
    int ty = t / (BN / TN);
    int m0 = blockIdx.x * BM, n0 = blockIdx.y * BN;
    int K = K1 + K2;
    unsigned long long acc2[TM][TN / 2] = {};   // packed f32x2 accumulators

    for (int k0 = 0; k0 < K; k0 += BK) {
#pragma unroll
        for (int l = 0; l < BM * BK / 4 / NTH; l++) {
            int fidx = t + l * NTH;
            int row = fidx / (BK / 4);
            int c4  = (fidx % (BK / 4)) * 4;
            int gm = m0 + row;
            int k = k0 + c4;
            float4 av = make_float4(0.f, 0.f, 0.f, 0.f);
            if (gm < M) {
                if (k < K1) av = *(const float4*)(A1 + (size_t)gm * K1 + k);
                else        av = *(const float4*)(A2 + (size_t)gm * K2 + (k - K1));
            }
            As[c4 + 0][row] = av.x;
            As[c4 + 1][row] = av.y;
            As[c4 + 2][row] = av.z;
            As[c4 + 3][row] = av.w;
        }
#pragma unroll
        for (int l = 0; l < BK * BN / 4 / NTH; l++) {
            int fidx = t + l * NTH;
            int brow = fidx / (BN / 4);
            int bc4  = (fidx % (BN / 4)) * 4;
            *(float4*)&Bs[brow][bc4] =
                *(const float4*)(B + (size_t)(k0 + brow) * Ncols + n0 + bc4);
        }
        __syncthreads();
#pragma unroll
        for (int kk = 0; kk < BK; kk++) {
            float af[TM], bf[TN];
#pragma unroll
            for (int i = 0; i < TM; i += 4)
                *(float4*)&af[i] = *(const float4*)&As[kk][ty * TM + i];
#pragma unroll
            for (int j = 0; j < TN; j += 4)
                *(float4*)&bf[j] = *(const float4*)&Bs[kk][tx * TN + j];
            unsigned long long bb[TN / 2];
#pragma unroll
            for (int j = 0; j < TN / 2; j++) PACK2(bb[j], bf[2 * j], bf[2 * j + 1]);
#pragma unroll
            for (int i = 0; i < TM; i++) {
                unsigned long long aa;
                PACK2(aa, af[i], af[i]);
#pragma unroll
                for (int j = 0; j < TN / 2; j++) FMA2(acc2[i][j], aa, bb[j]);
            }
        }
        __syncthreads();
    }
#pragma unroll
    for (int i = 0; i < TM; i++) {
        int gm = m0 + ty * TM + i;
        if (gm < M) {
#pragma unroll
            for (int j = 0; j < TN; j += 4) {
                int gn = n0 + tx * TN + j;
                float4 v;
                UNPACK2(v.x, v.y, acc2[i][j / 2]);
                UNPACK2(v.z, v.w, acc2[i][j / 2 + 1]);
                if (bias) {
                    v.x += bias[gn + 0]; v.y += bias[gn + 1];
                    v.z += bias[gn + 2]; v.w += bias[gn + 3];
                }
                *(float4*)(C + (size_t)gm * Ncols + gn) = v;
            }
        }
    }
}

// ---------------- per-node prep: el/er dots + gate pre-projection ----------
__global__ void k_node(const float* __restrict__ x,
                       const float* __restrict__ attn_l,
                       const float* __restrict__ attn_r,
                       const float* __restrict__ W_gate) {
    int w = (blockIdx.x * blockDim.x + threadIdx.x) >> 5;
    if (w >= NN) return;
    int lane = threadIdx.x & 31;

    const float4* fp = (const float4*)(d_feat + (size_t)w * 256 + lane * 8);
    float4 f0 = fp[0], f1 = fp[1];
    const float4* al = (const float4*)(attn_l + lane * 8);
    const float4* ar = (const float4*)(attn_r + lane * 8);
    float4 a0 = al[0], a1 = al[1];
    float4 r0 = ar[0], r1 = ar[1];
    float sl = f0.x * a0.x + f0.y * a0.y + f0.z * a0.z + f0.w * a0.w
             + f1.x * a1.x + f1.y * a1.y + f1.z * a1.z + f1.w * a1.w;
    float sr = f0.x * r0.x + f0.y * r0.y + f0.z * r0.z + f0.w * r0.w
             + f1.x * r1.x + f1.y * r1.y + f1.z * r1.z + f1.w * r1.w;
#pragma unroll
    for (int o = 1; o < 8; o <<= 1) {
        sl += __shfl_xor_sync(0xffffffffu, sl, o);
        sr += __shfl_xor_sync(0xffffffffu, sr, o);
    }
    if ((lane & 7) == 0) {
        d_el[w * 4 + (lane >> 3)] = sl;
        d_er[w * 4 + (lane >> 3)] = sr;
    }

    float4 xv = *(const float4*)(x + (size_t)w * 128 + lane * 4);
    const float4* Wg4 = (const float4*)W_gate;
    float s0 = 0, s1 = 0, s2 = 0, s3 = 0;
    float q0 = 0, q1 = 0, q2 = 0, q3 = 0;
    float xa[4] = { xv.x, xv.y, xv.z, xv.w };
#pragma unroll
    for (int i = 0; i < 4; i++) {
        float4 ws = __ldg(&Wg4[lane * 4 + i]);
        float4 wm = __ldg(&Wg4[192 + lane * 4 + i]);
        s0 += xa[i] * ws.x; s1 += xa[i] * ws.y; s2 += xa[i] * ws.z; s3 += xa[i] * ws.w;
        q0 += xa[i] * wm.x; q1 += xa[i] * wm.y; q2 += xa[i] * wm.z; q3 += xa[i] * wm.w;
    }
#pragma unroll
    for (int o = 16; o; o >>= 1) {
        s0 += __shfl_xor_sync(0xffffffffu, s0, o);
        s1 += __shfl_xor_sync(0xffffffffu, s1, o);
        s2 += __shfl_xor_sync(0xffffffffu, s2, o);
        s3 += __shfl_xor_sync(0xffffffffu, s3, o);
        q0 += __shfl_xor_sync(0xffffffffu, q0, o);
        q1 += __shfl_xor_sync(0xffffffffu, q1, o);
        q2 += __shfl_xor_sync(0xffffffffu, q2, o);
        q3 += __shfl_xor_sync(0xffffffffu, q3, o);
    }
    if (lane == 0) {
        *(float4*)(d_gs  + w * 4) = make_float4(s0, s1, s2, s3);
        *(float4*)(d_gmn + w * 4) = make_float4(q0, q1, q2, q3);
    }
}

// ---------------- fused single-pass aggregation: one warp per dst ----------
__global__ void k_agg(const float* __restrict__ W_gate,
                      const float* __restrict__ b_gate,
                      const float* __restrict__ b_gat) {
    int w = (blockIdx.x * blockDim.x + threadIdx.x) >> 5;
    if (w >= NN) return;
    int lane = threadIdx.x & 31;
    int h = lane >> 3;
    int beg = d_rowoff[w], end = d_rowoff[w + 1];
    float erh = __ldg(d_er + w * 4 + h);

    float mz0 = -FLT_MAX, mz1 = -FLT_MAX;
    float sg0 = 0, sg1 = 0, sg2 = 0, sg3 = 0;
    float mh = -FLT_MAX, dh = 0.f;
    float a0 = 0, a1 = 0, a2 = 0, a3 = 0, a4 = 0, a5 = 0, a6 = 0, a7 = 0;

    int s = (beg < end) ? __ldg(d_srt + beg) : 0;
    for (int p = beg; p < end; p++) {
        int s_next = (p + 1 < end) ? __ldg(d_srt + p + 1) : 0;
        float2 zv = *(const float2*)(d_z + (size_t)s * 64 + lane * 2);
        float4 gv = __ldg((const float4*)(d_gmn + s * 4));
        float elh = __ldg(d_el + s * 4 + h);
        const float4* fp = (const float4*)(d_feat + (size_t)s * 256 + lane * 8);
        float4 f0 = fp[0], f1 = fp[1];

        mz0 = fmaxf(mz0, zv.x); mz1 = fmaxf(mz1, zv.y);
        sg0 += gv.x; sg1 += gv.y; sg2 += gv.z; sg3 += gv.w;
        float e = lrelu(elh + erh);
        float mnew = fmaxf(mh, e);
        float corr = __expf(mh - mnew);
        float wgt  = __expf(e - mnew);
        mh = mnew;
        dh = dh * corr + wgt;
        a0 = a0 * corr + wgt * f0.x; a1 = a1 * corr + wgt * f0.y;
        a2 = a2 * corr + wgt * f0.z; a3 = a3 * corr + wgt * f0.w;
        a4 = a4 * corr + wgt * f1.x; a5 = a5 * corr + wgt * f1.y;
        a6 = a6 * corr + wgt * f1.z; a7 = a7 * corr + wgt * f1.w;
        s = s_next;
    }

    int deg = end - beg;
    if (deg == 0) { mz0 = 0.f; mz1 = 0.f; }
    float invm = 1.f / (float)(deg > 1 ? deg : 1);

    const float4* Wg4 = (const float4*)W_gate;
    float4 wz0 = __ldg(&Wg4[128 + 2 * lane]);
    float4 wz1 = __ldg(&Wg4[129 + 2 * lane]);
    float t0 = mz0 * wz0.x + mz1 * wz1.x;
    float t1 = mz0 * wz0.y + mz1 * wz1.y;
    float t2 = mz0 * wz0.z + mz1 * wz1.z;
    float t3 = mz0 * wz0.w + mz1 * wz1.w;
#pragma unroll
    for (int o = 16; o; o >>= 1) {
        t0 += __shfl_xor_sync(0xffffffffu, t0, o);
        t1 += __shfl_xor_sync(0xffffffffu, t1, o);
        t2 += __shfl_xor_sync(0xffffffffu, t2, o);
        t3 += __shfl_xor_sync(0xffffffffu, t3, o);
    }
    float4 gsv = *(const float4*)(d_gs + w * 4);
    float4 bg  = *(const float4*)b_gate;
    t0 += gsv.x + sg0 * invm + bg.x;
    t1 += gsv.y + sg1 * invm + bg.y;
    t2 += gsv.z + sg2 * invm + bg.z;
    t3 += gsv.w + sg3 * invm + bg.w;
    float g0 = 1.f / (1.f + __expf(-t0));
    float g1 = 1.f / (1.f + __expf(-t1));
    float g2 = 1.f / (1.f + __expf(-t2));
    float g3 = 1.f / (1.f + __expf(-t3));
    float gh = h == 0 ? g0 : (h == 1 ? g1 : (h == 2 ? g2 : g3));

    float invd = dh > 0.f ? 1.f / dh : 0.f;
    float accs[8] = { a0, a1, a2, a3, a4, a5, a6, a7 };
#pragma unroll
    for (int i = 0; i < 8; i++) {
        float ao = accs[i] * invd + __ldg(b_gat + lane * 8 + i);
        float c = gh * ao;
        c += __shfl_xor_sync(0xffffffffu, c, 8);
        c += __shfl_xor_sync(0xffffffffu, c, 16);
        if (lane < 8) d_gated[(size_t)w * 64 + lane * 8 + i] = 0.25f * c;
    }
}

// ---------------- launch ----------------------------------------------------
extern "C" void kernel_launch(void* const* d_in, const int* in_sizes, int n_in,
                              void* d_out, int out_size) {
    const float* x       = (const float*)d_in[0];
    const int*   ei      = (const int*)d_in[1];
    const float* W_gm    = (const float*)d_in[2];
    const float* b_gm    = (const float*)d_in[3];
    const float* W_gate  = (const float*)d_in[4];
    const float* b_gate  = (const float*)d_in[5];
    const float* W_fc    = (const float*)d_in[6];
    const float* attn_l  = (const float*)d_in[7];
    const float* attn_r  = (const float*)d_in[8];
    const float* b_gat   = (const float*)d_in[9];
    const float* W_merge = (const float*)d_in[10];
    const float* b_merge = (const float*)d_in[11];
    float* out = (float*)d_out;

    const int* src = ei;
    const int* dst = ei + EE;

    float *feat, *zbuf, *gated;
    int *degp, *curp;
    cudaGetSymbolAddress((void**)&feat,  d_feat);
    cudaGetSymbolAddress((void**)&zbuf,  d_z);
    cudaGetSymbolAddress((void**)&gated, d_gated);
    cudaGetSymbolAddress((void**)&degp,  d_deg);
    cudaGetSymbolAddress((void**)&curp,  d_cur);

    const int NB = (NN + 1023) / 1024;  // 49
    int warp_blocks = (NN * 32 + 255) / 256;

    // CSR prefix
    cudaMemsetAsync(degp, 0, NN * sizeof(int));
    cudaMemsetAsync(curp, 0, NN * sizeof(int));
    k_count<<<(EE + 255) / 256, 256>>>(dst);
    k_blocksum<<<NB, 1024>>>();
    k_scanbsum<<<1, 64>>>(NB);
    k_scanfinal<<<NB, 1024>>>();

    // big feat GEMM  (128x128 tile, 16x8 micro, 128 threads)
    dim3 gfeat((NN + 127) / 128, 2);
    k_gemm<128, 128, 16, 8><<<gfeat, 128>>>(x, 128, nullptr, 0, W_fc, nullptr, feat, NN, 256);

    k_scatter<<<(EE + 255) / 256, 256>>>(src, dst);

    // z GEMM (256x64 tile)
    dim3 gz((NN + 255) / 256, 1);
    k_gemm<256, 64, 16, 8><<<gz, 128>>>(x, 128, nullptr, 0, W_gm, b_gm, zbuf, NN, 64);

    k_node<<<warp_blocks, 256>>>(x, attn_l, attn_r, W_gate);
    k_agg<<<warp_blocks, 256>>>(W_gate, b_gate, b_gat);

    // merge GEMM (256x64 tile, K=192)
    dim3 gm((NN + 255) / 256, 1);
    k_gemm<256, 64, 16, 8><<<gm, 128>>>(x, 128, gated, 64, W_merge, b_merge, out, NN, 64);
}

// round 8
// speedup vs baseline: 1.1389x; 1.1389x over previous
#include <cuda_runtime.h>
#include <float.h>

#define NN 50000
#define EE 800000

// ---------------- scratch (no allocation allowed -> __device__ globals) ----
__device__ float d_feat[(size_t)NN * 256];   // x @ W_fc           [N,H*OUT]
__device__ float d_z[(size_t)NN * 64];       // x @ W_gm + b_gm    [N,MAP]
__device__ float d_el[NN * 4];               // attn_l dot         [N,H]
__device__ float d_er[NN * 4];               // attn_r dot         [N,H]
__device__ float d_gs[NN * 4];               // x @ W_gate[0:128]  [N,H]
__device__ float d_gmn[NN * 4];              // x @ W_gate[192:]   [N,H]
__device__ float d_gated[(size_t)NN * 64];   // gated head-mean    [N,OUT]
__device__ int   d_deg[NN];
__device__ int   d_cur[NN];
__device__ int   d_rowoff[NN + 1];
__device__ int   d_srt[EE];                  // src ids sorted by dst (CSR)
__device__ int   d_bsum[64];
__device__ int   d_bpre[64];

__device__ __forceinline__ float lrelu(float v) { return v > 0.f ? v : 0.2f * v; }

#define PACK2(out, lo, hi) \
    asm("mov.b64 %0, {%1, %2};" : "=l"(out) : "r"(__float_as_uint(lo)), "r"(__float_as_uint(hi)))
#define UNPACK2(lo, hi, in) \
    do { unsigned _ulo, _uhi; \
         asm("mov.b64 {%0, %1}, %2;" : "=r"(_ulo), "=r"(_uhi) : "l"(in)); \
         lo = __uint_as_float(_ulo); hi = __uint_as_float(_uhi); } while (0)
#define FMA2(acc, a, b) \
    asm("fma.rn.f32x2 %0, %1, %2, %0;" : "+l"(acc) : "l"(a), "l"(b))

// ---------------- CSR build ------------------------------------------------
__global__ void k_count(const int* __restrict__ dst) {
    int e = blockIdx.x * blockDim.x + threadIdx.x;
    if (e < EE) atomicAdd(&d_deg[dst[e]], 1);
}

__global__ void k_blocksum() {
    __shared__ int sh[1024];
    int i = blockIdx.x * 1024 + threadIdx.x;
    sh[threadIdx.x] = (i < NN) ? d_deg[i] : 0;
    __syncthreads();
    for (int s = 512; s; s >>= 1) {
        if (threadIdx.x < s) sh[threadIdx.x] += sh[threadIdx.x + s];
        __syncthreads();
    }
    if (threadIdx.x == 0) d_bsum[blockIdx.x] = sh[0];
}

__global__ void k_scanbsum(int nb) {
    __shared__ int sh[64];
    int t = threadIdx.x;
    int v = (t < nb) ? d_bsum[t] : 0;
    sh[t] = v;
    __syncthreads();
    for (int o = 1; o < 64; o <<= 1) {
        int u = (t >= o) ? sh[t - o] : 0;
        __syncthreads();
        sh[t] += u;
        __syncthreads();
    }
    if (t < nb) d_bpre[t] = sh[t] - v;
}

__global__ void k_scanfinal() {
    __shared__ int sh[1024];
    int tid = threadIdx.x;
    int i = blockIdx.x * 1024 + tid;
    int v = (i < NN) ? d_deg[i] : 0;
    sh[tid] = v;
    __syncthreads();
    for (int off = 1; off < 1024; off <<= 1) {
        int t = (tid >= off) ? sh[tid - off] : 0;
        __syncthreads();
        sh[tid] += t;
        __syncthreads();
    }
    if (i < NN) d_rowoff[i] = d_bpre[blockIdx.x] + sh[tid] - v;
    if (i == 0) d_rowoff[NN] = EE;
}

__global__ void k_scatter(const int* __restrict__ src, const int* __restrict__ dst) {
    int e = blockIdx.x * blockDim.x + threadIdx.x;
    if (e < EE) {
        int d = dst[e];
        int p = d_rowoff[d] + atomicAdd(&d_cur[d], 1);
        d_srt[p] = src[e];
    }
}

// ---------------- tiled fp32 GEMM with packed FFMA2 (R5-proven config) -----
// BMxBN block tile, 256 threads, TMxTN micro-tile, BK=16.
template<int BM, int BN, int TM, int TN>
__global__ void k_gemm(const float* __restrict__ A1, int K1,
                       const float* __restrict__ A2, int K2,
                       const float* __restrict__ B,
                       const float* __restrict__ bias,
                       float* __restrict__ C, int M, int Ncols) {
    constexpr int BK = 16;
    constexpr int NTH = (BM / TM) * (BN / TN);   // must be 256
    __shared__ __align__(16) float As[BK][BM + 4];
    __shared__ __align__(16) float Bs[BK][BN + 4];
    int t = threadIdx.x;
    int tx = t % (BN / TN);
    int ty = t / (BN / TN);
    int m0 = blockIdx.x * BM, n0 = blockIdx.y * BN;
    int K = K1 + K2;
    unsigned long long acc2[TM][TN / 2] = {};   // packed f32x2 accumulators

    for (int k0 = 0; k0 < K; k0 += BK) {
#pragma unroll
        for (int l = 0; l < BM * BK / 4 / NTH; l++) {
            int fidx = t + l * NTH;
            int row = fidx / (BK / 4);
            int c4  = (fidx % (BK / 4)) * 4;
            int gm = m0 + row;
            int k = k0 + c4;
            float4 av = make_float4(0.f, 0.f, 0.f, 0.f);
            if (gm < M) {
                if (k < K1) av = *(const float4*)(A1 + (size_t)gm * K1 + k);
                else        av = *(const float4*)(A2 + (size_t)gm * K2 + (k - K1));
            }
            As[c4 + 0][row] = av.x;
            As[c4 + 1][row] = av.y;
            As[c4 + 2][row] = av.z;
            As[c4 + 3][row] = av.w;
        }
#pragma unroll
        for (int l = 0; l < BK * BN / 4 / NTH; l++) {
            int fidx = t + l * NTH;
            int brow = fidx / (BN / 4);
            int bc4  = (fidx % (BN / 4)) * 4;
            *(float4*)&Bs[brow][bc4] =
                *(const float4*)(B + (size_t)(k0 + brow) * Ncols + n0 + bc4);
        }
        __syncthreads();
#pragma unroll
        for (int kk = 0; kk < BK; kk++) {
            float af[TM], bf[TN];
#pragma unroll
            for (int i = 0; i < TM; i += 4)
                *(float4*)&af[i] = *(const float4*)&As[kk][ty * TM + i];
#pragma unroll
            for (int j = 0; j < TN; j += 4)
                *(float4*)&bf[j] = *(const float4*)&Bs[kk][tx * TN + j];
            unsigned long long bb[TN / 2];
#pragma unroll
            for (int j = 0; j < TN / 2; j++) PACK2(bb[j], bf[2 * j], bf[2 * j + 1]);
#pragma unroll
            for (int i = 0; i < TM; i++) {
                unsigned long long aa;
                PACK2(aa, af[i], af[i]);
#pragma unroll
                for (int j = 0; j < TN / 2; j++) FMA2(acc2[i][j], aa, bb[j]);
            }
        }
        __syncthreads();
    }
#pragma unroll
    for (int i = 0; i < TM; i++) {
        int gm = m0 + ty * TM + i;
        if (gm < M) {
#pragma unroll
            for (int j = 0; j < TN; j += 4) {
                int gn = n0 + tx * TN + j;
                float4 v;
                UNPACK2(v.x, v.y, acc2[i][j / 2]);
                UNPACK2(v.z, v.w, acc2[i][j / 2 + 1]);
                if (bias) {
                    v.x += bias[gn + 0]; v.y += bias[gn + 1];
                    v.z += bias[gn + 2]; v.w += bias[gn + 3];
                }
                *(float4*)(C + (size_t)gm * Ncols + gn) = v;
            }
        }
    }
}

// ---------------- per-node prep: el/er dots + gate pre-projection ----------
__global__ void k_node(const float* __restrict__ x,
                       const float* __restrict__ attn_l,
                       const float* __restrict__ attn_r,
                       const float* __restrict__ W_gate) {
    int w = (blockIdx.x * blockDim.x + threadIdx.x) >> 5;
    if (w >= NN) return;
    int lane = threadIdx.x & 31;

    const float4* fp = (const float4*)(d_feat + (size_t)w * 256 + lane * 8);
    float4 f0 = fp[0], f1 = fp[1];
    const float4* al = (const float4*)(attn_l + lane * 8);
    const float4* ar = (const float4*)(attn_r + lane * 8);
    float4 a0 = al[0], a1 = al[1];
    float4 r0 = ar[0], r1 = ar[1];
    float sl = f0.x * a0.x + f0.y * a0.y + f0.z * a0.z + f0.w * a0.w
             + f1.x * a1.x + f1.y * a1.y + f1.z * a1.z + f1.w * a1.w;
    float sr = f0.x * r0.x + f0.y * r0.y + f0.z * r0.z + f0.w * r0.w
             + f1.x * r1.x + f1.y * r1.y + f1.z * r1.z + f1.w * r1.w;
#pragma unroll
    for (int o = 1; o < 8; o <<= 1) {
        sl += __shfl_xor_sync(0xffffffffu, sl, o);
        sr += __shfl_xor_sync(0xffffffffu, sr, o);
    }
    if ((lane & 7) == 0) {
        d_el[w * 4 + (lane >> 3)] = sl;
        d_er[w * 4 + (lane >> 3)] = sr;
    }

    float4 xv = *(const float4*)(x + (size_t)w * 128 + lane * 4);
    const float4* Wg4 = (const float4*)W_gate;
    float s0 = 0, s1 = 0, s2 = 0, s3 = 0;
    float q0 = 0, q1 = 0, q2 = 0, q3 = 0;
    float xa[4] = { xv.x, xv.y, xv.z, xv.w };
#pragma unroll
    for (int i = 0; i < 4; i++) {
        float4 ws = __ldg(&Wg4[lane * 4 + i]);
        float4 wm = __ldg(&Wg4[192 + lane * 4 + i]);
        s0 += xa[i] * ws.x; s1 += xa[i] * ws.y; s2 += xa[i] * ws.z; s3 += xa[i] * ws.w;
        q0 += xa[i] * wm.x; q1 += xa[i] * wm.y; q2 += xa[i] * wm.z; q3 += xa[i] * wm.w;
    }
#pragma unroll
    for (int o = 16; o; o >>= 1) {
        s0 += __shfl_xor_sync(0xffffffffu, s0, o);
        s1 += __shfl_xor_sync(0xffffffffu, s1, o);
        s2 += __shfl_xor_sync(0xffffffffu, s2, o);
        s3 += __shfl_xor_sync(0xffffffffu, s3, o);
        q0 += __shfl_xor_sync(0xffffffffu, q0, o);
        q1 += __shfl_xor_sync(0xffffffffu, q1, o);
        q2 += __shfl_xor_sync(0xffffffffu, q2, o);
        q3 += __shfl_xor_sync(0xffffffffu, q3, o);
    }
    if (lane == 0) {
        *(float4*)(d_gs  + w * 4) = make_float4(s0, s1, s2, s3);
        *(float4*)(d_gmn + w * 4) = make_float4(q0, q1, q2, q3);
    }
}

// ---------------- fused single-pass aggregation, 2-way unrolled ------------
__global__ void k_agg(const float* __restrict__ W_gate,
                      const float* __restrict__ b_gate,
                      const float* __restrict__ b_gat) {
    int w = (blockIdx.x * blockDim.x + threadIdx.x) >> 5;
    if (w >= NN) return;
    int lane = threadIdx.x & 31;
    int h = lane >> 3;
    int beg = d_rowoff[w], end = d_rowoff[w + 1];
    float erh = __ldg(d_er + w * 4 + h);

    float mz0 = -FLT_MAX, mz1 = -FLT_MAX;
    float sg0 = 0, sg1 = 0, sg2 = 0, sg3 = 0;

    // two independent online-softmax streams (even/odd edges)
    float mA = -FLT_MAX, dA = 0.f;
    float A0 = 0, A1 = 0, A2 = 0, A3 = 0, A4 = 0, A5 = 0, A6 = 0, A7 = 0;
    float mB = -FLT_MAX, dB = 0.f;
    float B0 = 0, B1 = 0, B2 = 0, B3 = 0, B4 = 0, B5 = 0, B6 = 0, B7 = 0;

    int p = beg;
    for (; p + 1 < end; p += 2) {
        int sa = __ldg(d_srt + p);
        int sb = __ldg(d_srt + p + 1);

        float2 za = *(const float2*)(d_z + (size_t)sa * 64 + lane * 2);
        float2 zb = *(const float2*)(d_z + (size_t)sb * 64 + lane * 2);
        float4 ga = __ldg((const float4*)(d_gmn + sa * 4));
        float4 gb = __ldg((const float4*)(d_gmn + sb * 4));
        float ea_ = __ldg(d_el + sa * 4 + h);
        float eb_ = __ldg(d_el + sb * 4 + h);
        const float4* fa = (const float4*)(d_feat + (size_t)sa * 256 + lane * 8);
        const float4* fb = (const float4*)(d_feat + (size_t)sb * 256 + lane * 8);
        float4 fa0 = fa[0], fa1 = fa[1];
        float4 fb0 = fb[0], fb1 = fb[1];

        mz0 = fmaxf(mz0, fmaxf(za.x, zb.x));
        mz1 = fmaxf(mz1, fmaxf(za.y, zb.y));
        sg0 += ga.x + gb.x; sg1 += ga.y + gb.y;
        sg2 += ga.z + gb.z; sg3 += ga.w + gb.w;

        float eA = lrelu(ea_ + erh);
        float mnA = fmaxf(mA, eA);
        float cA = __expf(mA - mnA);
        float wA = __expf(eA - mnA);
        mA = mnA;
        dA = dA * cA + wA;
        A0 = A0 * cA + wA * fa0.x; A1 = A1 * cA + wA * fa0.y;
        A2 = A2 * cA + wA * fa0.z; A3 = A3 * cA + wA * fa0.w;
        A4 = A4 * cA + wA * fa1.x; A5 = A5 * cA + wA * fa1.y;
        A6 = A6 * cA + wA * fa1.z; A7 = A7 * cA + wA * fa1.w;

        float eB = lrelu(eb_ + erh);
        float mnB = fmaxf(mB, eB);
        float cB = __expf(mB - mnB);
        float wB = __expf(eB - mnB);
        mB = mnB;
        dB = dB * cB + wB;
        B0 = B0 * cB + wB * fb0.x; B1 = B1 * cB + wB * fb0.y;
        B2 = B2 * cB + wB * fb0.z; B3 = B3 * cB + wB * fb0.w;
        B4 = B4 * cB + wB * fb1.x; B5 = B5 * cB + wB * fb1.y;
        B6 = B6 * cB + wB * fb1.z; B7 = B7 * cB + wB * fb1.w;
    }
    if (p < end) {  // tail edge -> stream A
        int sa = __ldg(d_srt + p);
        float2 za = *(const float2*)(d_z + (size_t)sa * 64 + lane * 2);
        float4 ga = __ldg((const float4*)(d_gmn + sa * 4));
        float ea_ = __ldg(d_el + sa * 4 + h);
        const float4* fa = (const float4*)(d_feat + (size_t)sa * 256 + lane * 8);
        float4 fa0 = fa[0], fa1 = fa[1];
        mz0 = fmaxf(mz0, za.x); mz1 = fmaxf(mz1, za.y);
        sg0 += ga.x; sg1 += ga.y; sg2 += ga.z; sg3 += ga.w;
        float eA = lrelu(ea_ + erh);
        float mnA = fmaxf(mA, eA);
        float cA = __expf(mA - mnA);
        float wA = __expf(eA - mnA);
        mA = mnA;
        dA = dA * cA + wA;
        A0 = A0 * cA + wA * fa0.x; A1 = A1 * cA + wA * fa0.y;
        A2 = A2 * cA + wA * fa0.z; A3 = A3 * cA + wA * fa0.w;
        A4 = A4 * cA + wA * fa1.x; A5 = A5 * cA + wA * fa1.y;
        A6 = A6 * cA + wA * fa1.z; A7 = A7 * cA + wA * fa1.w;
    }

    // merge streams A and B
    float mh = fmaxf(mA, mB);
    float cA = (dA > 0.f) ? __expf(mA - mh) : 0.f;
    float cB = (dB > 0.f) ? __expf(mB - mh) : 0.f;
    float dh = dA * cA + dB * cB;
    float accs[8];
    accs[0] = A0 * cA + B0 * cB; accs[1] = A1 * cA + B1 * cB;
    accs[2] = A2 * cA + B2 * cB; accs[3] = A3 * cA + B3 * cB;
    accs[4] = A4 * cA + B4 * cB; accs[5] = A5 * cA + B5 * cB;
    accs[6] = A6 * cA + B6 * cB; accs[7] = A7 * cA + B7 * cB;

    int deg = end - beg;
    if (deg == 0) { mz0 = 0.f; mz1 = 0.f; }
    float invm = 1.f / (float)(deg > 1 ? deg : 1);

    const float4* Wg4 = (const float4*)W_gate;
    float4 wz0 = __ldg(&Wg4[128 + 2 * lane]);
    float4 wz1 = __ldg(&Wg4[129 + 2 * lane]);
    float t0 = mz0 * wz0.x + mz1 * wz1.x;
    float t1 = mz0 * wz0.y + mz1 * wz1.y;
    float t2 = mz0 * wz0.z + mz1 * wz1.z;
    float t3 = mz0 * wz0.w + mz1 * wz1.w;
#pragma unroll
    for (int o = 16; o; o >>= 1) {
        t0 += __shfl_xor_sync(0xffffffffu, t0, o);
        t1 += __shfl_xor_sync(0xffffffffu, t1, o);
        t2 += __shfl_xor_sync(0xffffffffu, t2, o);
        t3 += __shfl_xor_sync(0xffffffffu, t3, o);
    }
    float4 gsv = *(const float4*)(d_gs + w * 4);
    float4 bg  = *(const float4*)b_gate;
    t0 += gsv.x + sg0 * invm + bg.x;
    t1 += gsv.y + sg1 * invm + bg.y;
    t2 += gsv.z + sg2 * invm + bg.z;
    t3 += gsv.w + sg3 * invm + bg.w;
    float g0 = 1.f / (1.f + __expf(-t0));
    float g1 = 1.f / (1.f + __expf(-t1));
    float g2 = 1.f / (1.f + __expf(-t2));
    float g3 = 1.f / (1.f + __expf(-t3));
    float gh = h == 0 ? g0 : (h == 1 ? g1 : (h == 2 ? g2 : g3));

    float invd = dh > 0.f ? 1.f / dh : 0.f;
#pragma unroll
    for (int i = 0; i < 8; i++) {
        float ao = accs[i] * invd + __ldg(b_gat + lane * 8 + i);
        float c = gh * ao;
        c += __shfl_xor_sync(0xffffffffu, c, 8);
        c += __shfl_xor_sync(0xffffffffu, c, 16);
        if (lane < 8) d_gated[(size_t)w * 64 + lane * 8 + i] = 0.25f * c;
    }
}

// ---------------- launch ----------------------------------------------------
extern "C" void kernel_launch(void* const* d_in, const int* in_sizes, int n_in,
                              void* d_out, int out_size) {
    const float* x       = (const float*)d_in[0];
    const int*   ei      = (const int*)d_in[1];
    const float* W_gm    = (const float*)d_in[2];
    const float* b_gm    = (const float*)d_in[3];
    const float* W_gate  = (const float*)d_in[4];
    const float* b_gate  = (const float*)d_in[5];
    const float* W_fc    = (const float*)d_in[6];
    const float* attn_l  = (const float*)d_in[7];
    const float* attn_r  = (const float*)d_in[8];
    const float* b_gat   = (const float*)d_in[9];
    const float* W_merge = (const float*)d_in[10];
    const float* b_merge = (const float*)d_in[11];
    float* out = (float*)d_out;

    const int* src = ei;
    const int* dst = ei + EE;

    float *feat, *zbuf, *gated;
    int *degp, *curp;
    cudaGetSymbolAddress((void**)&feat,  d_feat);
    cudaGetSymbolAddress((void**)&zbuf,  d_z);
    cudaGetSymbolAddress((void**)&gated, d_gated);
    cudaGetSymbolAddress((void**)&degp,  d_deg);
    cudaGetSymbolAddress((void**)&curp,  d_cur);

    const int NB = (NN + 1023) / 1024;  // 49
    int warp_blocks = (NN * 32 + 255) / 256;

    // launches 1-5: memset x2, count, blocksum, scanbsum
    cudaMemsetAsync(degp, 0, NN * sizeof(int));
    cudaMemsetAsync(curp, 0, NN * sizeof(int));
    k_count<<<(EE + 255) / 256, 256>>>(dst);
    k_blocksum<<<NB, 1024>>>();
    k_scanbsum<<<1, 64>>>(NB);

    // launch 6 — captured by ncu (-s 5 -c 1): the big feat GEMM
    dim3 gfeat((NN + 127) / 128, 2);
    k_gemm<128, 128, 8, 8><<<gfeat, 256>>>(x, 128, nullptr, 0, W_fc, nullptr, feat, NN, 256);

    k_scanfinal<<<NB, 1024>>>();
    k_scatter<<<(EE + 255) / 256, 256>>>(src, dst);

    dim3 gz((NN + 127) / 128, 1);
    k_gemm<128, 64, 8, 4><<<gz, 256>>>(x, 128, nullptr, 0, W_gm, b_gm, zbuf, NN, 64);

    k_node<<<warp_blocks, 256>>>(x, attn_l, attn_r, W_gate);
    k_agg<<<warp_blocks, 256>>>(W_gate, b_gate, b_gat);

    dim3 gm((NN + 127) / 128, 1);
    k_gemm<128, 64, 8, 4><<<gm, 256>>>(x, 128, gated, 64, W_merge, b_merge, out, NN, 64);
}

// round 9
// speedup vs baseline: 1.1634x; 1.0215x over previous
#include <cuda_runtime.h>
#include <float.h>

#define NN 50000
#define EE 800000

// ---------------- scratch (no allocation allowed -> __device__ globals) ----
__device__ float d_feat[(size_t)NN * 256];   // x @ W_fc           [N,H*OUT]
__device__ float d_z[(size_t)NN * 64];       // x @ W_gm + b_gm    [N,MAP]
__device__ float d_el[NN * 4];               // attn_l dot         [N,H]
__device__ float d_er[NN * 4];               // attn_r dot         [N,H]
__device__ float d_gs[NN * 4];               // x @ W_gate[0:128]  [N,H]
__device__ float d_gmn[NN * 4];              // x @ W_gate[192:]   [N,H]
__device__ float d_gated[(size_t)NN * 64];   // gated head-mean    [N,OUT]
__device__ int   d_deg[NN];
__device__ int   d_cur[NN];
__device__ int   d_rowoff[NN + 1];
__device__ int   d_srt[EE];                  // src ids sorted by dst (CSR)
__device__ int   d_bsum[64];
__device__ int   d_bpre[64];

__device__ __forceinline__ float lrelu(float v) { return v > 0.f ? v : 0.2f * v; }

#define PACK2(out, lo, hi) \
    asm("mov.b64 %0, {%1, %2};" : "=l"(out) : "r"(__float_as_uint(lo)), "r"(__float_as_uint(hi)))
#define UNPACK2(lo, hi, in) \
    do { unsigned _ulo, _uhi; \
         asm("mov.b64 {%0, %1}, %2;" : "=r"(_ulo), "=r"(_uhi) : "l"(in)); \
         lo = __uint_as_float(_ulo); hi = __uint_as_float(_uhi); } while (0)
#define FMA2(acc, a, b) \
    asm("fma.rn.f32x2 %0, %1, %2, %0;" : "+l"(acc) : "l"(a), "l"(b))

// ---------------- CSR build ------------------------------------------------
__global__ void k_count(const int* __restrict__ dst) {
    int e = blockIdx.x * blockDim.x + threadIdx.x;
    if (e < EE) atomicAdd(&d_deg[dst[e]], 1);
}

__global__ void k_blocksum() {
    __shared__ int sh[1024];
    int i = blockIdx.x * 1024 + threadIdx.x;
    sh[threadIdx.x] = (i < NN) ? d_deg[i] : 0;
    __syncthreads();
    for (int s = 512; s; s >>= 1) {
        if (threadIdx.x < s) sh[threadIdx.x] += sh[threadIdx.x + s];
        __syncthreads();
    }
    if (threadIdx.x == 0) d_bsum[blockIdx.x] = sh[0];
}

__global__ void k_scanbsum(int nb) {
    __shared__ int sh[64];
    int t = threadIdx.x;
    int v = (t < nb) ? d_bsum[t] : 0;
    sh[t] = v;
    __syncthreads();
    for (int o = 1; o < 64; o <<= 1) {
        int u = (t >= o) ? sh[t - o] : 0;
        __syncthreads();
        sh[t] += u;
        __syncthreads();
    }
    if (t < nb) d_bpre[t] = sh[t] - v;
}

__global__ void k_scanfinal() {
    __shared__ int sh[1024];
    int tid = threadIdx.x;
    int i = blockIdx.x * 1024 + tid;
    int v = (i < NN) ? d_deg[i] : 0;
    sh[tid] = v;
    __syncthreads();
    for (int off = 1; off < 1024; off <<= 1) {
        int t = (tid >= off) ? sh[tid - off] : 0;
        __syncthreads();
        sh[tid] += t;
        __syncthreads();
    }
    if (i < NN) d_rowoff[i] = d_bpre[blockIdx.x] + sh[tid] - v;
    if (i == 0) d_rowoff[NN] = EE;
}

__global__ void k_scatter(const int* __restrict__ src, const int* __restrict__ dst) {
    int e = blockIdx.x * blockDim.x + threadIdx.x;
    if (e < EE) {
        int d = dst[e];
        int p = d_rowoff[d] + atomicAdd(&d_cur[d], 1);
        d_srt[p] = src[e];
    }
}

// ---------------- tiled fp32 GEMM, FFMA2 + register-staged double buffer ---
// One __syncthreads per K-slab; LDG for slab i+1 issued before compute of i.
template<int BM, int BN, int TM, int TN, int MINB>
__global__ void __launch_bounds__((BM / TM) * (BN / TN), MINB)
k_gemm(const float* __restrict__ A1, int K1,
       const float* __restrict__ A2, int K2,
       const float* __restrict__ B,
       const float* __restrict__ bias,
       float* __restrict__ C, int M, int Ncols) {
    constexpr int BK = 16;
    constexpr int NTH = (BM / TM) * (BN / TN);
    constexpr int AL = BM * BK / 4 / NTH;     // A float4 per thread per slab
    constexpr int BL = BK * BN / 4 / NTH;     // B float4 per thread per slab
    __shared__ __align__(16) float As[2][BK][BM + 4];
    __shared__ __align__(16) float Bs[2][BK][BN + 4];
    int t = threadIdx.x;
    int tx = t % (BN / TN);
    int ty = t / (BN / TN);
    int m0 = blockIdx.x * BM, n0 = blockIdx.y * BN;
    int K = K1 + K2;
    int nIter = K / BK;
    unsigned long long acc2[TM][TN / 2] = {};

    float4 aReg[AL], bReg[BL];

    // prologue: load slab 0 into registers
#pragma unroll
    for (int l = 0; l < AL; l++) {
        int fidx = t + l * NTH;
        int row = fidx / (BK / 4);
        int c4  = (fidx % (BK / 4)) * 4;
        int gm = m0 + row;
        float4 av = make_float4(0.f, 0.f, 0.f, 0.f);
        if (gm < M) {
            if (c4 < K1) av = *(const float4*)(A1 + (size_t)gm * K1 + c4);
            else         av = *(const float4*)(A2 + (size_t)gm * K2 + (c4 - K1));
        }
        aReg[l] = av;
    }
#pragma unroll
    for (int l = 0; l < BL; l++) {
        int fidx = t + l * NTH;
        int brow = fidx / (BN / 4);
        int bc4  = (fidx % (BN / 4)) * 4;
        bReg[l] = *(const float4*)(B + (size_t)brow * Ncols + n0 + bc4);
    }

    int s = 0;
    for (int it = 0; it < nIter; it++) {
        // store staged regs into smem buffer s
#pragma unroll
        for (int l = 0; l < AL; l++) {
            int fidx = t + l * NTH;
            int row = fidx / (BK / 4);
            int c4  = (fidx % (BK / 4)) * 4;
            As[s][c4 + 0][row] = aReg[l].x;
            As[s][c4 + 1][row] = aReg[l].y;
            As[s][c4 + 2][row] = aReg[l].z;
            As[s][c4 + 3][row] = aReg[l].w;
        }
#pragma unroll
        for (int l = 0; l < BL; l++) {
            int fidx = t + l * NTH;
            int brow = fidx / (BN / 4);
            int bc4  = (fidx % (BN / 4)) * 4;
            *(float4*)&Bs[s][brow][bc4] = bReg[l];
        }
        __syncthreads();

        // prefetch next slab into registers (latency hidden by compute)
        if (it + 1 < nIter) {
            int k0 = (it + 1) * BK;
#pragma unroll
            for (int l = 0; l < AL; l++) {
                int fidx = t + l * NTH;
                int row = fidx / (BK / 4);
                int c4  = (fidx % (BK / 4)) * 4;
                int gm = m0 + row;
                int k = k0 + c4;
                float4 av = make_float4(0.f, 0.f, 0.f, 0.f);
                if (gm < M) {
                    if (k < K1) av = *(const float4*)(A1 + (size_t)gm * K1 + k);
                    else        av = *(const float4*)(A2 + (size_t)gm * K2 + (k - K1));
                }
                aReg[l] = av;
            }
#pragma unroll
            for (int l = 0; l < BL; l++) {
                int fidx = t + l * NTH;
                int brow = fidx / (BN / 4);
                int bc4  = (fidx % (BN / 4)) * 4;
                bReg[l] = *(const float4*)(B + (size_t)(k0 + brow) * Ncols + n0 + bc4);
            }
        }

        // compute on buffer s
#pragma unroll
        for (int kk = 0; kk < BK; kk++) {
            float af[TM], bf[TN];
#pragma unroll
            for (int i = 0; i < TM; i += 4)
                *(float4*)&af[i] = *(const float4*)&As[s][kk][ty * TM + i];
#pragma unroll
            for (int j = 0; j < TN; j += 4)
                *(float4*)&bf[j] = *(const float4*)&Bs[s][kk][tx * TN + j];
            unsigned long long bb[TN / 2];
#pragma unroll
            for (int j = 0; j < TN / 2; j++) PACK2(bb[j], bf[2 * j], bf[2 * j + 1]);
#pragma unroll
            for (int i = 0; i < TM; i++) {
                unsigned long long aa;
                PACK2(aa, af[i], af[i]);
#pragma unroll
                for (int j = 0; j < TN / 2; j++) FMA2(acc2[i][j], aa, bb[j]);
            }
        }
        s ^= 1;
    }

#pragma unroll
    for (int i = 0; i < TM; i++) {
        int gm = m0 + ty * TM + i;
        if (gm < M) {
#pragma unroll
            for (int j = 0; j < TN; j += 4) {
                int gn = n0 + tx * TN + j;
                float4 v;
                UNPACK2(v.x, v.y, acc2[i][j / 2]);
                UNPACK2(v.z, v.w, acc2[i][j / 2 + 1]);
                if (bias) {
                    v.x += bias[gn + 0]; v.y += bias[gn + 1];
                    v.z += bias[gn + 2]; v.w += bias[gn + 3];
                }
                *(float4*)(C + (size_t)gm * Ncols + gn) = v;
            }
        }
    }
}

// ---------------- per-node prep: el/er dots + gate pre-projection ----------
__global__ void k_node(const float* __restrict__ x,
                       const float* __restrict__ attn_l,
                       const float* __restrict__ attn_r,
                       const float* __restrict__ W_gate) {
    int w = (blockIdx.x * blockDim.x + threadIdx.x) >> 5;
    if (w >= NN) return;
    int lane = threadIdx.x & 31;

    const float4* fp = (const float4*)(d_feat + (size_t)w * 256 + lane * 8);
    float4 f0 = fp[0], f1 = fp[1];
    const float4* al = (const float4*)(attn_l + lane * 8);
    const float4* ar = (const float4*)(attn_r + lane * 8);
    float4 a0 = al[0], a1 = al[1];
    float4 r0 = ar[0], r1 = ar[1];
    float sl = f0.x * a0.x + f0.y * a0.y + f0.z * a0.z + f0.w * a0.w
             + f1.x * a1.x + f1.y * a1.y + f1.z * a1.z + f1.w * a1.w;
    float sr = f0.x * r0.x + f0.y * r0.y + f0.z * r0.z + f0.w * r0.w
             + f1.x * r1.x + f1.y * r1.y + f1.z * r1.z + f1.w * r1.w;
#pragma unroll
    for (int o = 1; o < 8; o <<= 1) {
        sl += __shfl_xor_sync(0xffffffffu, sl, o);
        sr += __shfl_xor_sync(0xffffffffu, sr, o);
    }
    if ((lane & 7) == 0) {
        d_el[w * 4 + (lane >> 3)] = sl;
        d_er[w * 4 + (lane >> 3)] = sr;
    }

    float4 xv = *(const float4*)(x + (size_t)w * 128 + lane * 4);
    const float4* Wg4 = (const float4*)W_gate;
    float s0 = 0, s1 = 0, s2 = 0, s3 = 0;
    float q0 = 0, q1 = 0, q2 = 0, q3 = 0;
    float xa[4] = { xv.x, xv.y, xv.z, xv.w };
#pragma unroll
    for (int i = 0; i < 4; i++) {
        float4 ws = __ldg(&Wg4[lane * 4 + i]);
        float4 wm = __ldg(&Wg4[192 + lane * 4 + i]);
        s0 += xa[i] * ws.x; s1 += xa[i] * ws.y; s2 += xa[i] * ws.z; s3 += xa[i] * ws.w;
        q0 += xa[i] * wm.x; q1 += xa[i] * wm.y; q2 += xa[i] * wm.z; q3 += xa[i] * wm.w;
    }
#pragma unroll
    for (int o = 16; o; o >>= 1) {
        s0 += __shfl_xor_sync(0xffffffffu, s0, o);
        s1 += __shfl_xor_sync(0xffffffffu, s1, o);
        s2 += __shfl_xor_sync(0xffffffffu, s2, o);
        s3 += __shfl_xor_sync(0xffffffffu, s3, o);
        q0 += __shfl_xor_sync(0xffffffffu, q0, o);
        q1 += __shfl_xor_sync(0xffffffffu, q1, o);
        q2 += __shfl_xor_sync(0xffffffffu, q2, o);
        q3 += __shfl_xor_sync(0xffffffffu, q3, o);
    }
    if (lane == 0) {
        *(float4*)(d_gs  + w * 4) = make_float4(s0, s1, s2, s3);
        *(float4*)(d_gmn + w * 4) = make_float4(q0, q1, q2, q3);
    }
}

// ---------------- fused single-pass aggregation, 2-way unrolled ------------
__global__ void k_agg(const float* __restrict__ W_gate,
                      const float* __restrict__ b_gate,
                      const float* __restrict__ b_gat) {
    int w = (blockIdx.x * blockDim.x + threadIdx.x) >> 5;
    if (w >= NN) return;
    int lane = threadIdx.x & 31;
    int h = lane >> 3;
    int beg = d_rowoff[w], end = d_rowoff[w + 1];
    float erh = __ldg(d_er + w * 4 + h);

    float mz0 = -FLT_MAX, mz1 = -FLT_MAX;
    float sg0 = 0, sg1 = 0, sg2 = 0, sg3 = 0;

    float mA = -FLT_MAX, dA = 0.f;
    float A0 = 0, A1 = 0, A2 = 0, A3 = 0, A4 = 0, A5 = 0, A6 = 0, A7 = 0;
    float mB = -FLT_MAX, dB = 0.f;
    float B0 = 0, B1 = 0, B2 = 0, B3 = 0, B4 = 0, B5 = 0, B6 = 0, B7 = 0;

    int p = beg;
    for (; p + 1 < end; p += 2) {
        int sa = __ldg(d_srt + p);
        int sb = __ldg(d_srt + p + 1);

        float2 za = *(const float2*)(d_z + (size_t)sa * 64 + lane * 2);
        float2 zb = *(const float2*)(d_z + (size_t)sb * 64 + lane * 2);
        float4 ga = __ldg((const float4*)(d_gmn + sa * 4));
        float4 gb = __ldg((const float4*)(d_gmn + sb * 4));
        float ea_ = __ldg(d_el + sa * 4 + h);
        float eb_ = __ldg(d_el + sb * 4 + h);
        const float4* fa = (const float4*)(d_feat + (size_t)sa * 256 + lane * 8);
        const float4* fb = (const float4*)(d_feat + (size_t)sb * 256 + lane * 8);
        float4 fa0 = fa[0], fa1 = fa[1];
        float4 fb0 = fb[0], fb1 = fb[1];

        mz0 = fmaxf(mz0, fmaxf(za.x, zb.x));
        mz1 = fmaxf(mz1, fmaxf(za.y, zb.y));
        sg0 += ga.x + gb.x; sg1 += ga.y + gb.y;
        sg2 += ga.z + gb.z; sg3 += ga.w + gb.w;

        float eA = lrelu(ea_ + erh);
        float mnA = fmaxf(mA, eA);
        float cA = __expf(mA - mnA);
        float wA = __expf(eA - mnA);
        mA = mnA;
        dA = dA * cA + wA;
        A0 = A0 * cA + wA * fa0.x; A1 = A1 * cA + wA * fa0.y;
        A2 = A2 * cA + wA * fa0.z; A3 = A3 * cA + wA * fa0.w;
        A4 = A4 * cA + wA * fa1.x; A5 = A5 * cA + wA * fa1.y;
        A6 = A6 * cA + wA * fa1.z; A7 = A7 * cA + wA * fa1.w;

        float eB = lrelu(eb_ + erh);
        float mnB = fmaxf(mB, eB);
        float cB = __expf(mB - mnB);
        float wB = __expf(eB - mnB);
        mB = mnB;
        dB = dB * cB + wB;
        B0 = B0 * cB + wB * fb0.x; B1 = B1 * cB + wB * fb0.y;
        B2 = B2 * cB + wB * fb0.z; B3 = B3 * cB + wB * fb0.w;
        B4 = B4 * cB + wB * fb1.x; B5 = B5 * cB + wB * fb1.y;
        B6 = B6 * cB + wB * fb1.z; B7 = B7 * cB + wB * fb1.w;
    }
    if (p < end) {
        int sa = __ldg(d_srt + p);
        float2 za = *(const float2*)(d_z + (size_t)sa * 64 + lane * 2);
        float4 ga = __ldg((const float4*)(d_gmn + sa * 4));
        float ea_ = __ldg(d_el + sa * 4 + h);
        const float4* fa = (const float4*)(d_feat + (size_t)sa * 256 + lane * 8);
        float4 fa0 = fa[0], fa1 = fa[1];
        mz0 = fmaxf(mz0, za.x); mz1 = fmaxf(mz1, za.y);
        sg0 += ga.x; sg1 += ga.y; sg2 += ga.z; sg3 += ga.w;
        float eA = lrelu(ea_ + erh);
        float mnA = fmaxf(mA, eA);
        float cA = __expf(mA - mnA);
        float wA = __expf(eA - mnA);
        mA = mnA;
        dA = dA * cA + wA;
        A0 = A0 * cA + wA * fa0.x; A1 = A1 * cA + wA * fa0.y;
        A2 = A2 * cA + wA * fa0.z; A3 = A3 * cA + wA * fa0.w;
        A4 = A4 * cA + wA * fa1.x; A5 = A5 * cA + wA * fa1.y;
        A6 = A6 * cA + wA * fa1.z; A7 = A7 * cA + wA * fa1.w;
    }

    float mh = fmaxf(mA, mB);
    float cA = (dA > 0.f) ? __expf(mA - mh) : 0.f;
    float cB = (dB > 0.f) ? __expf(mB - mh) : 0.f;
    float dh = dA * cA + dB * cB;
    float accs[8];
    accs[0] = A0 * cA + B0 * cB; accs[1] = A1 * cA + B1 * cB;
    accs[2] = A2 * cA + B2 * cB; accs[3] = A3 * cA + B3 * cB;
    accs[4] = A4 * cA + B4 * cB; accs[5] = A5 * cA + B5 * cB;
    accs[6] = A6 * cA + B6 * cB; accs[7] = A7 * cA + B7 * cB;

    int deg = end - beg;
    if (deg == 0) { mz0 = 0.f; mz1 = 0.f; }
    float invm = 1.f / (float)(deg > 1 ? deg : 1);

    const float4* Wg4 = (const float4*)W_gate;
    float4 wz0 = __ldg(&Wg4[128 + 2 * lane]);
    float4 wz1 = __ldg(&Wg4[129 + 2 * lane]);
    float t0 = mz0 * wz0.x + mz1 * wz1.x;
    float t1 = mz0 * wz0.y + mz1 * wz1.y;
    float t2 = mz0 * wz0.z + mz1 * wz1.z;
    float t3 = mz0 * wz0.w + mz1 * wz1.w;
#pragma unroll
    for (int o = 16; o; o >>= 1) {
        t0 += __shfl_xor_sync(0xffffffffu, t0, o);
        t1 += __shfl_xor_sync(0xffffffffu, t1, o);
        t2 += __shfl_xor_sync(0xffffffffu, t2, o);
        t3 += __shfl_xor_sync(0xffffffffu, t3, o);
    }
    float4 gsv = *(const float4*)(d_gs + w * 4);
    float4 bg  = *(const float4*)b_gate;
    t0 += gsv.x + sg0 * invm + bg.x;
    t1 += gsv.y + sg1 * invm + bg.y;
    t2 += gsv.z + sg2 * invm + bg.z;
    t3 += gsv.w + sg3 * invm + bg.w;
    float g0 = 1.f / (1.f + __expf(-t0));
    float g1 = 1.f / (1.f + __expf(-t1));
    float g2 = 1.f / (1.f + __expf(-t2));
    float g3 = 1.f / (1.f + __expf(-t3));
    float gh = h == 0 ? g0 : (h == 1 ? g1 : (h == 2 ? g2 : g3));

    float invd = dh > 0.f ? 1.f / dh : 0.f;
#pragma unroll
    for (int i = 0; i < 8; i++) {
        float ao = accs[i] * invd + __ldg(b_gat + lane * 8 + i);
        float c = gh * ao;
        c += __shfl_xor_sync(0xffffffffu, c, 8);
        c += __shfl_xor_sync(0xffffffffu, c, 16);
        if (lane < 8) d_gated[(size_t)w * 64 + lane * 8 + i] = 0.25f * c;
    }
}

// ---------------- launch ----------------------------------------------------
extern "C" void kernel_launch(void* const* d_in, const int* in_sizes, int n_in,
                              void* d_out, int out_size) {
    const float* x       = (const float*)d_in[0];
    const int*   ei      = (const int*)d_in[1];
    const float* W_gm    = (const float*)d_in[2];
    const float* b_gm    = (const float*)d_in[3];
    const float* W_gate  = (const float*)d_in[4];
    const float* b_gate  = (const float*)d_in[5];
    const float* W_fc    = (const float*)d_in[6];
    const float* attn_l  = (const float*)d_in[7];
    const float* attn_r  = (const float*)d_in[8];
    const float* b_gat   = (const float*)d_in[9];
    const float* W_merge = (const float*)d_in[10];
    const float* b_merge = (const float*)d_in[11];
    float* out = (float*)d_out;

    const int* src = ei;
    const int* dst = ei + EE;

    float *feat, *zbuf, *gated;
    int *degp, *curp;
    cudaGetSymbolAddress((void**)&feat,  d_feat);
    cudaGetSymbolAddress((void**)&zbuf,  d_z);
    cudaGetSymbolAddress((void**)&gated, d_gated);
    cudaGetSymbolAddress((void**)&degp,  d_deg);
    cudaGetSymbolAddress((void**)&curp,  d_cur);

    const int NB = (NN + 1023) / 1024;  // 49
    int warp_blocks = (NN * 32 + 255) / 256;

    // launches 1-5: memset x2, count, blocksum, scanbsum
    cudaMemsetAsync(degp, 0, NN * sizeof(int));
    cudaMemsetAsync(curp, 0, NN * sizeof(int));
    k_count<<<(EE + 255) / 256, 256>>>(dst);
    k_blocksum<<<NB, 1024>>>();
    k_scanbsum<<<1, 64>>>(NB);

    // launch 6 — captured by ncu (-s 5 -c 1): the big feat GEMM
    dim3 gfeat((NN + 127) / 128, 2);
    k_gemm<128, 128, 8, 8, 2><<<gfeat, 256>>>(x, 128, nullptr, 0, W_fc, nullptr, feat, NN, 256);

    k_scanfinal<<<NB, 1024>>>();
    k_scatter<<<(EE + 255) / 256, 256>>>(src, dst);

    // z GEMM: 128x64 tile, 128 threads, 8x8 micro
    dim3 gz((NN + 127) / 128, 1);
    k_gemm<128, 64, 8, 8, 4><<<gz, 128>>>(x, 128, nullptr, 0, W_gm, b_gm, zbuf, NN, 64);

    k_node<<<warp_blocks, 256>>>(x, attn_l, attn_r, W_gate);
    k_agg<<<warp_blocks, 256>>>(W_gate, b_gate, b_gat);

    // merge GEMM: 128x64 tile, 128 threads, K=192
    dim3 gm((NN + 127) / 128, 1);
    k_gemm<128, 64, 8, 8, 4><<<gm, 128>>>(x, 128, gated, 64, W_merge, b_merge, out, NN, 64);
}

// round 15
// speedup vs baseline: 1.2437x; 1.0690x over previous
#include <cuda_runtime.h>
#include <cuda_fp16.h>
#include <float.h>

#define NN 50000
#define EE 800000

// ---------------- scratch (no allocation allowed -> __device__ globals) ----
__device__ __half d_feat_h[(size_t)NN * 256]; // x @ W_fc (fp16)    [N,H*OUT]
__device__ __half d_z_h[(size_t)NN * 64];     // x @ W_gm + b (fp16)[N,MAP]
__device__ float d_el[NN * 4];                // attn_l dot         [N,H]
__device__ float d_er[NN * 4];                // attn_r dot         [N,H]
__device__ float d_gs[NN * 4];                // x @ W_gate[0:128]  [N,H]
__device__ float d_gmn[NN * 4];               // x @ W_gate[192:]   [N,H]
__device__ float d_gated[(size_t)NN * 64];    // gated head-mean    [N,OUT]
__device__ int   d_deg[NN];
__device__ int   d_cur[NN];
__device__ int   d_rowoff[NN + 1];
__device__ int   d_srt[EE];                   // src ids sorted by dst (CSR)
__device__ int   d_bsum[64];
__device__ int   d_bpre[64];

__device__ __forceinline__ float lrelu(float v) { return v > 0.f ? v : 0.2f * v; }

#define PACK2(out, lo, hi) \
    asm("mov.b64 %0, {%1, %2};" : "=l"(out) : "r"(__float_as_uint(lo)), "r"(__float_as_uint(hi)))
#define UNPACK2(lo, hi, in) \
    do { unsigned _ulo, _uhi; \
         asm("mov.b64 {%0, %1}, %2;" : "=r"(_ulo), "=r"(_uhi) : "l"(in)); \
         lo = __uint_as_float(_ulo); hi = __uint_as_float(_uhi); } while (0)
#define FMA2(acc, a, b) \
    asm("fma.rn.f32x2 %0, %1, %2, %0;" : "+l"(acc) : "l"(a), "l"(b))

// ---------------- CSR build ------------------------------------------------
__global__ void k_count(const int* __restrict__ dst) {
    int e = blockIdx.x * blockDim.x + threadIdx.x;
    if (e < EE) atomicAdd(&d_deg[dst[e]], 1);
}

__global__ void k_blocksum() {
    __shared__ int sh[1024];
    int i = blockIdx.x * 1024 + threadIdx.x;
    sh[threadIdx.x] = (i < NN) ? d_deg[i] : 0;
    __syncthreads();
    for (int s = 512; s; s >>= 1) {
        if (threadIdx.x < s) sh[threadIdx.x] += sh[threadIdx.x + s];
        __syncthreads();
    }
    if (threadIdx.x == 0) d_bsum[blockIdx.x] = sh[0];
}

__global__ void k_scanbsum(int nb) {
    __shared__ int sh[64];
    int t = threadIdx.x;
    int v = (t < nb) ? d_bsum[t] : 0;
    sh[t] = v;
    __syncthreads();
    for (int o = 1; o < 64; o <<= 1) {
        int u = (t >= o) ? sh[t - o] : 0;
        __syncthreads();
        sh[t] += u;
        __syncthreads();
    }
    if (t < nb) d_bpre[t] = sh[t] - v;
}

__global__ void k_scanfinal() {
    __shared__ int sh[1024];
    int tid = threadIdx.x;
    int i = blockIdx.x * 1024 + tid;
    int v = (i < NN) ? d_deg[i] : 0;
    sh[tid] = v;
    __syncthreads();
    for (int off = 1; off < 1024; off <<= 1) {
        int t = (tid >= off) ? sh[tid - off] : 0;
        __syncthreads();
        sh[tid] += t;
        __syncthreads();
    }
    if (i < NN) d_rowoff[i] = d_bpre[blockIdx.x] + sh[tid] - v;
    if (i == 0) d_rowoff[NN] = EE;
}

__global__ void k_scatter(const int* __restrict__ src, const int* __restrict__ dst) {
    int e = blockIdx.x * blockDim.x + threadIdx.x;
    if (e < EE) {
        int d = dst[e];
        int p = d_rowoff[d] + atomicAdd(&d_cur[d], 1);
        d_srt[p] = src[e];
    }
}

// ---------------- tiled fp32 GEMM, FFMA2 + reg-staged double buffer --------
// HALF_OUT: epilogue converts to __half and writes to (half*)C.
template<int BM, int BN, int TM, int TN, int MINB, bool HALF_OUT>
__global__ void __launch_bounds__((BM / TM) * (BN / TN), MINB)
k_gemm(const float* __restrict__ A1, int K1,
       const float* __restrict__ A2, int K2,
       const float* __restrict__ B,
       const float* __restrict__ bias,
       void* __restrict__ Cv, int M, int Ncols) {
    constexpr int BK = 16;
    constexpr int NTH = (BM / TM) * (BN / TN);
    constexpr int AL = BM * BK / 4 / NTH;
    constexpr int BL = BK * BN / 4 / NTH;
    __shared__ __align__(16) float As[2][BK][BM + 4];
    __shared__ __align__(16) float Bs[2][BK][BN + 4];
    int t = threadIdx.x;
    int tx = t % (BN / TN);
    int ty = t / (BN / TN);
    int m0 = blockIdx.x * BM, n0 = blockIdx.y * BN;
    int K = K1 + K2;
    int nIter = K / BK;
    unsigned long long acc2[TM][TN / 2] = {};

    float4 aReg[AL], bReg[BL];

#pragma unroll
    for (int l = 0; l < AL; l++) {
        int fidx = t + l * NTH;
        int row = fidx / (BK / 4);
        int c4  = (fidx % (BK / 4)) * 4;
        int gm = m0 + row;
        float4 av = make_float4(0.f, 0.f, 0.f, 0.f);
        if (gm < M) {
            if (c4 < K1) av = *(const float4*)(A1 + (size_t)gm * K1 + c4);
            else         av = *(const float4*)(A2 + (size_t)gm * K2 + (c4 - K1));
        }
        aReg[l] = av;
    }
#pragma unroll
    for (int l = 0; l < BL; l++) {
        int fidx = t + l * NTH;
        int brow = fidx / (BN / 4);
        int bc4  = (fidx % (BN / 4)) * 4;
        bReg[l] = *(const float4*)(B + (size_t)brow * Ncols + n0 + bc4);
    }

    int s = 0;
    for (int it = 0; it < nIter; it++) {
#pragma unroll
        for (int l = 0; l < AL; l++) {
            int fidx = t + l * NTH;
            int row = fidx / (BK / 4);
            int c4  = (fidx % (BK / 4)) * 4;
            As[s][c4 + 0][row] = aReg[l].x;
            As[s][c4 + 1][row] = aReg[l].y;
            As[s][c4 + 2][row] = aReg[l].z;
            As[s][c4 + 3][row] = aReg[l].w;
        }
#pragma unroll
        for (int l = 0; l < BL; l++) {
            int fidx = t + l * NTH;
            int brow = fidx / (BN / 4);
            int bc4  = (fidx % (BN / 4)) * 4;
            *(float4*)&Bs[s][brow][bc4] = bReg[l];
        }
        __syncthreads();

        if (it + 1 < nIter) {
            int k0 = (it + 1) * BK;
#pragma unroll
            for (int l = 0; l < AL; l++) {
                int fidx = t + l * NTH;
                int row = fidx / (BK / 4);
                int c4  = (fidx % (BK / 4)) * 4;
                int gm = m0 + row;
                int k = k0 + c4;
                float4 av = make_float4(0.f, 0.f, 0.f, 0.f);
                if (gm < M) {
                    if (k < K1) av = *(const float4*)(A1 + (size_t)gm * K1 + k);
                    else        av = *(const float4*)(A2 + (size_t)gm * K2 + (k - K1));
                }
                aReg[l] = av;
            }
#pragma unroll
            for (int l = 0; l < BL; l++) {
                int fidx = t + l * NTH;
                int brow = fidx / (BN / 4);
                int bc4  = (fidx % (BN / 4)) * 4;
                bReg[l] = *(const float4*)(B + (size_t)(k0 + brow) * Ncols + n0 + bc4);
            }
        }

#pragma unroll
        for (int kk = 0; kk < BK; kk++) {
            float af[TM], bf[TN];
#pragma unroll
            for (int i = 0; i < TM; i += 4)
                *(float4*)&af[i] = *(const float4*)&As[s][kk][ty * TM + i];
#pragma unroll
            for (int j = 0; j < TN; j += 4)
                *(float4*)&bf[j] = *(const float4*)&Bs[s][kk][tx * TN + j];
            unsigned long long bb[TN / 2];
#pragma unroll
            for (int j = 0; j < TN / 2; j++) PACK2(bb[j], bf[2 * j], bf[2 * j + 1]);
#pragma unroll
            for (int i = 0; i < TM; i++) {
                unsigned long long aa;
                PACK2(aa, af[i], af[i]);
#pragma unroll
                for (int j = 0; j < TN / 2; j++) FMA2(acc2[i][j], aa, bb[j]);
            }
        }
        s ^= 1;
    }

#pragma unroll
    for (int i = 0; i < TM; i++) {
        int gm = m0 + ty * TM + i;
        if (gm < M) {
#pragma unroll
            for (int j = 0; j < TN; j += 4) {
                int gn = n0 + tx * TN + j;
                float4 v;
                UNPACK2(v.x, v.y, acc2[i][j / 2]);
                UNPACK2(v.z, v.w, acc2[i][j / 2 + 1]);
                if (bias) {
                    v.x += bias[gn + 0]; v.y += bias[gn + 1];
                    v.z += bias[gn + 2]; v.w += bias[gn + 3];
                }
                if (HALF_OUT) {
                    __half2 h0 = __floats2half2_rn(v.x, v.y);
                    __half2 h1 = __floats2half2_rn(v.z, v.w);
                    __half2* cp = (__half2*)((__half*)Cv + (size_t)gm * Ncols + gn);
                    cp[0] = h0; cp[1] = h1;
                } else {
                    *(float4*)((float*)Cv + (size_t)gm * Ncols + gn) = v;
                }
            }
        }
    }
}

// ---------------- per-node prep: el/er dots + gate pre-projection ----------
__global__ void k_node(const float* __restrict__ x,
                       const float* __restrict__ attn_l,
                       const float* __restrict__ attn_r,
                       const float* __restrict__ W_gate) {
    int w = (blockIdx.x * blockDim.x + threadIdx.x) >> 5;
    if (w >= NN) return;
    int lane = threadIdx.x & 31;

    // feat (fp16) -> el/er dots
    uint4 u = *(const uint4*)(d_feat_h + (size_t)w * 256 + lane * 8);
    __half2 hh[4];
    hh[0] = *(__half2*)&u.x; hh[1] = *(__half2*)&u.y;
    hh[2] = *(__half2*)&u.z; hh[3] = *(__half2*)&u.w;
    float f[8];
#pragma unroll
    for (int i = 0; i < 4; i++) {
        float2 fv = __half22float2(hh[i]);
        f[2 * i] = fv.x; f[2 * i + 1] = fv.y;
    }
    const float4* al = (const float4*)(attn_l + lane * 8);
    const float4* ar = (const float4*)(attn_r + lane * 8);
    float4 a0 = al[0], a1 = al[1];
    float4 r0 = ar[0], r1 = ar[1];
    float sl = f[0] * a0.x + f[1] * a0.y + f[2] * a0.z + f[3] * a0.w
             + f[4] * a1.x + f[5] * a1.y + f[6] * a1.z + f[7] * a1.w;
    float sr = f[0] * r0.x + f[1] * r0.y + f[2] * r0.z + f[3] * r0.w
             + f[4] * r1.x + f[5] * r1.y + f[6] * r1.z + f[7] * r1.w;
#pragma unroll
    for (int o = 1; o < 8; o <<= 1) {
        sl += __shfl_xor_sync(0xffffffffu, sl, o);
        sr += __shfl_xor_sync(0xffffffffu, sr, o);
    }
    if ((lane & 7) == 0) {
        d_el[w * 4 + (lane >> 3)] = sl;
        d_er[w * 4 + (lane >> 3)] = sr;
    }

    float4 xv = *(const float4*)(x + (size_t)w * 128 + lane * 4);
    const float4* Wg4 = (const float4*)W_gate;
    float s0 = 0, s1 = 0, s2 = 0, s3 = 0;
    float q0 = 0, q1 = 0, q2 = 0, q3 = 0;
    float xa[4] = { xv.x, xv.y, xv.z, xv.w };
#pragma unroll
    for (int i = 0; i < 4; i++) {
        float4 ws = __ldg(&Wg4[lane * 4 + i]);
        float4 wm = __ldg(&Wg4[192 + lane * 4 + i]);
        s0 += xa[i] * ws.x; s1 += xa[i] * ws.y; s2 += xa[i] * ws.z; s3 += xa[i] * ws.w;
        q0 += xa[i] * wm.x; q1 += xa[i] * wm.y; q2 += xa[i] * wm.z; q3 += xa[i] * wm.w;
    }
#pragma unroll
    for (int o = 16; o; o >>= 1) {
        s0 += __shfl_xor_sync(0xffffffffu, s0, o);
        s1 += __shfl_xor_sync(0xffffffffu, s1, o);
        s2 += __shfl_xor_sync(0xffffffffu, s2, o);
        s3 += __shfl_xor_sync(0xffffffffu, s3, o);
        q0 += __shfl_xor_sync(0xffffffffu, q0, o);
        q1 += __shfl_xor_sync(0xffffffffu, q1, o);
        q2 += __shfl_xor_sync(0xffffffffu, q2, o);
        q3 += __shfl_xor_sync(0xffffffffu, q3, o);
    }
    if (lane == 0) {
        *(float4*)(d_gs  + w * 4) = make_float4(s0, s1, s2, s3);
        *(float4*)(d_gmn + w * 4) = make_float4(q0, q1, q2, q3);
    }
}

// ---------------- fused single-pass aggregation, 2-way unrolled, fp16 reads -
__global__ void k_agg(const float* __restrict__ W_gate,
                      const float* __restrict__ b_gate,
                      const float* __restrict__ b_gat) {
    int w = (blockIdx.x * blockDim.x + threadIdx.x) >> 5;
    if (w >= NN) return;
    int lane = threadIdx.x & 31;
    int h = lane >> 3;
    int beg = d_rowoff[w], end = d_rowoff[w + 1];
    float erh = __ldg(d_er + w * 4 + h);

    float mz0 = -FLT_MAX, mz1 = -FLT_MAX;
    float sg0 = 0, sg1 = 0, sg2 = 0, sg3 = 0;

    float mA = -FLT_MAX, dA = 0.f;
    float A0 = 0, A1 = 0, A2 = 0, A3 = 0, A4 = 0, A5 = 0, A6 = 0, A7 = 0;
    float mB = -FLT_MAX, dB = 0.f;
    float B0 = 0, B1 = 0, B2 = 0, B3 = 0, B4 = 0, B5 = 0, B6 = 0, B7 = 0;

    int p = beg;
    for (; p + 1 < end; p += 2) {
        int sa = __ldg(d_srt + p);
        int sb = __ldg(d_srt + p + 1);

        __half2 zha = *(const __half2*)(d_z_h + (size_t)sa * 64 + lane * 2);
        __half2 zhb = *(const __half2*)(d_z_h + (size_t)sb * 64 + lane * 2);
        float2 za = __half22float2(zha);
        float2 zb = __half22float2(zhb);
        float4 ga = __ldg((const float4*)(d_gmn + sa * 4));
        float4 gb = __ldg((const float4*)(d_gmn + sb * 4));
        float ea_ = __ldg(d_el + sa * 4 + h);
        float eb_ = __ldg(d_el + sb * 4 + h);
        uint4 ua = *(const uint4*)(d_feat_h + (size_t)sa * 256 + lane * 8);
        uint4 ub = *(const uint4*)(d_feat_h + (size_t)sb * 256 + lane * 8);
        float2 fa0 = __half22float2(*(__half2*)&ua.x);
        float2 fa1 = __half22float2(*(__half2*)&ua.y);
        float2 fa2 = __half22float2(*(__half2*)&ua.z);
        float2 fa3 = __half22float2(*(__half2*)&ua.w);
        float2 fb0 = __half22float2(*(__half2*)&ub.x);
        float2 fb1 = __half22float2(*(__half2*)&ub.y);
        float2 fb2 = __half22float2(*(__half2*)&ub.z);
        float2 fb3 = __half22float2(*(__half2*)&ub.w);

        mz0 = fmaxf(mz0, fmaxf(za.x, zb.x));
        mz1 = fmaxf(mz1, fmaxf(za.y, zb.y));
        sg0 += ga.x + gb.x; sg1 += ga.y + gb.y;
        sg2 += ga.z + gb.z; sg3 += ga.w + gb.w;

        float eA = lrelu(ea_ + erh);
        float mnA = fmaxf(mA, eA);
        float cA = __expf(mA - mnA);
        float wA = __expf(eA - mnA);
        mA = mnA;
        dA = dA * cA + wA;
        A0 = A0 * cA + wA * fa0.x; A1 = A1 * cA + wA * fa0.y;
        A2 = A2 * cA + wA * fa1.x; A3 = A3 * cA + wA * fa1.y;
        A4 = A4 * cA + wA * fa2.x; A5 = A5 * cA + wA * fa2.y;
        A6 = A6 * cA + wA * fa3.x; A7 = A7 * cA + wA * fa3.y;

        float eB = lrelu(eb_ + erh);
        float mnB = fmaxf(mB, eB);
        float cB = __expf(mB - mnB);
        float wB = __expf(eB - mnB);
        mB = mnB;
        dB = dB * cB + wB;
        B0 = B0 * cB + wB * fb0.x; B1 = B1 * cB + wB * fb0.y;
        B2 = B2 * cB + wB * fb1.x; B3 = B3 * cB + wB * fb1.y;
        B4 = B4 * cB + wB * fb2.x; B5 = B5 * cB + wB * fb2.y;
        B6 = B6 * cB + wB * fb3.x; B7 = B7 * cB + wB * fb3.y;
    }
    if (p < end) {
        int sa = __ldg(d_srt + p);
        __half2 zha = *(const __half2*)(d_z_h + (size_t)sa * 64 + lane * 2);
        float2 za = __half22float2(zha);
        float4 ga = __ldg((const float4*)(d_gmn + sa * 4));
        float ea_ = __ldg(d_el + sa * 4 + h);
        uint4 ua = *(const uint4*)(d_feat_h + (size_t)sa * 256 + lane * 8);
        float2 fa0 = __half22float2(*(__half2*)&ua.x);
        float2 fa1 = __half22float2(*(__half2*)&ua.y);
        float2 fa2 = __half22float2(*(__half2*)&ua.z);
        float2 fa3 = __half22float2(*(__half2*)&ua.w);
        mz0 = fmaxf(mz0, za.x); mz1 = fmaxf(mz1, za.y);
        sg0 += ga.x; sg1 += ga.y; sg2 += ga.z; sg3 += ga.w;
        float eA = lrelu(ea_ + erh);
        float mnA = fmaxf(mA, eA);
        float cA = __expf(mA - mnA);
        float wA = __expf(eA - mnA);
        mA = mnA;
        dA = dA * cA + wA;
        A0 = A0 * cA + wA * fa0.x; A1 = A1 * cA + wA * fa0.y;
        A2 = A2 * cA + wA * fa1.x; A3 = A3 * cA + wA * fa1.y;
        A4 = A4 * cA + wA * fa2.x; A5 = A5 * cA + wA * fa2.y;
        A6 = A6 * cA + wA * fa3.x; A7 = A7 * cA + wA * fa3.y;
    }

    float mh = fmaxf(mA, mB);
    float cA = (dA > 0.f) ? __expf(mA - mh) : 0.f;
    float cB = (dB > 0.f) ? __expf(mB - mh) : 0.f;
    float dh = dA * cA + dB * cB;
    float accs[8];
    accs[0] = A0 * cA + B0 * cB; accs[1] = A1 * cA + B1 * cB;
    accs[2] = A2 * cA + B2 * cB; accs[3] = A3 * cA + B3 * cB;
    accs[4] = A4 * cA + B4 * cB; accs[5] = A5 * cA + B5 * cB;
    accs[6] = A6 * cA + B6 * cB; accs[7] = A7 * cA + B7 * cB;

    int deg = end - beg;
    if (deg == 0) { mz0 = 0.f; mz1 = 0.f; }
    float invm = 1.f / (float)(deg > 1 ? deg : 1);

    const float4* Wg4 = (const float4*)W_gate;
    float4 wz0 = __ldg(&Wg4[128 + 2 * lane]);
    float4 wz1 = __ldg(&Wg4[129 + 2 * lane]);
    float t0 = mz0 * wz0.x + mz1 * wz1.x;
    float t1 = mz0 * wz0.y + mz1 * wz1.y;
    float t2 = mz0 * wz0.z + mz1 * wz1.z;
    float t3 = mz0 * wz0.w + mz1 * wz1.w;
#pragma unroll
    for (int o = 16; o; o >>= 1) {
        t0 += __shfl_xor_sync(0xffffffffu, t0, o);
        t1 += __shfl_xor_sync(0xffffffffu, t1, o);
        t2 += __shfl_xor_sync(0xffffffffu, t2, o);
        t3 += __shfl_xor_sync(0xffffffffu, t3, o);
    }
    float4 gsv = *(const float4*)(d_gs + w * 4);
    float4 bg  = *(const float4*)b_gate;
    t0 += gsv.x + sg0 * invm + bg.x;
    t1 += gsv.y + sg1 * invm + bg.y;
    t2 += gsv.z + sg2 * invm + bg.z;
    t3 += gsv.w + sg3 * invm + bg.w;
    float g0 = 1.f / (1.f + __expf(-t0));
    float g1 = 1.f / (1.f + __expf(-t1));
    float g2 = 1.f / (1.f + __expf(-t2));
    float g3 = 1.f / (1.f + __expf(-t3));
    float gh = h == 0 ? g0 : (h == 1 ? g1 : (h == 2 ? g2 : g3));

    float invd = dh > 0.f ? 1.f / dh : 0.f;
#pragma unroll
    for (int i = 0; i < 8; i++) {
        float ao = accs[i] * invd + __ldg(b_gat + lane * 8 + i);
        float c = gh * ao;
        c += __shfl_xor_sync(0xffffffffu, c, 8);
        c += __shfl_xor_sync(0xffffffffu, c, 16);
        if (lane < 8) d_gated[(size_t)w * 64 + lane * 8 + i] = 0.25f * c;
    }
}

// ---------------- launch ----------------------------------------------------
extern "C" void kernel_launch(void* const* d_in, const int* in_sizes, int n_in,
                              void* d_out, int out_size) {
    const float* x       = (const float*)d_in[0];
    const int*   ei      = (const int*)d_in[1];
    const float* W_gm    = (const float*)d_in[2];
    const float* b_gm    = (const float*)d_in[3];
    const float* W_gate  = (const float*)d_in[4];
    const float* b_gate  = (const float*)d_in[5];
    const float* W_fc    = (const float*)d_in[6];
    const float* attn_l  = (const float*)d_in[7];
    const float* attn_r  = (const float*)d_in[8];
    const float* b_gat   = (const float*)d_in[9];
    const float* W_merge = (const float*)d_in[10];
    const float* b_merge = (const float*)d_in[11];
    float* out = (float*)d_out;

    const int* src = ei;
    const int* dst = ei + EE;

    void *feat_h, *z_h;
    float *gated;
    int *degp, *curp;
    cudaGetSymbolAddress(&feat_h, d_feat_h);
    cudaGetSymbolAddress(&z_h,    d_z_h);
    cudaGetSymbolAddress((void**)&gated, d_gated);
    cudaGetSymbolAddress((void**)&degp,  d_deg);
    cudaGetSymbolAddress((void**)&curp,  d_cur);

    const int NB = (NN + 1023) / 1024;  // 49
    int warp_blocks = (NN * 32 + 255) / 256;

    cudaMemsetAsync(degp, 0, NN * sizeof(int));
    cudaMemsetAsync(curp, 0, NN * sizeof(int));
    k_count<<<(EE + 255) / 256, 256>>>(dst);
    k_blocksum<<<NB, 1024>>>();
    k_scanbsum<<<1, 64>>>(NB);

    // launch 6 — captured by ncu: the big feat GEMM (fp16 out)
    dim3 gfeat((NN + 127) / 128, 2);
    k_gemm<128, 128, 8, 8, 2, true><<<gfeat, 256>>>(x, 128, nullptr, 0, W_fc, nullptr, feat_h, NN, 256);

    k_scanfinal<<<NB, 1024>>>();
    k_scatter<<<(EE + 255) / 256, 256>>>(src, dst);

    dim3 gz((NN + 127) / 128, 1);
    k_gemm<128, 64, 8, 8, 4, true><<<gz, 128>>>(x, 128, nullptr, 0, W_gm, b_gm, z_h, NN, 64);

    k_node<<<warp_blocks, 256>>>(x, attn_l, attn_r, W_gate);
    k_agg<<<warp_blocks, 256>>>(W_gate, b_gate, b_gat);

    dim3 gm((NN + 127) / 128, 1);
    k_gemm<128, 64, 8, 8, 4, false><<<gm, 128>>>(x, 128, gated, 64, W_merge, b_merge, out, NN, 64);
}

// round 16
// speedup vs baseline: 1.5137x; 1.2171x over previous
#include <cuda_runtime.h>
#include <cuda_fp16.h>
#include <float.h>

#define NN 50000
#define EE 800000

// ---------------- scratch ---------------------------------------------------
__device__ __half d_feat_h[(size_t)NN * 256]; // x @ W_fc (fp16)    [N,H*OUT]
__device__ __half d_z_h[(size_t)NN * 64];     // x @ W_gm + b (fp16)[N,MAP]
__device__ __half d_x_h[(size_t)NN * 128];    // x in fp16          [N,IN]
__device__ __half d_wfc_h[128 * 256];         // W_fc in fp16
__device__ float d_el[NN * 4];
__device__ float d_er[NN * 4];
__device__ float d_gs[NN * 4];
__device__ float d_gmn[NN * 4];
__device__ float d_gated[(size_t)NN * 64];
__device__ int   d_deg[NN];
__device__ int   d_cur[NN];
__device__ int   d_rowoff[NN + 1];
__device__ int   d_srt[EE];
__device__ int   d_bsum[64];
__device__ int   d_bpre[64];

__device__ __forceinline__ float lrelu(float v) { return v > 0.f ? v : 0.2f * v; }

#define PACK2(out, lo, hi) \
    asm("mov.b64 %0, {%1, %2};" : "=l"(out) : "r"(__float_as_uint(lo)), "r"(__float_as_uint(hi)))
#define UNPACK2(lo, hi, in) \
    do { unsigned _ulo, _uhi; \
         asm("mov.b64 {%0, %1}, %2;" : "=r"(_ulo), "=r"(_uhi) : "l"(in)); \
         lo = __uint_as_float(_ulo); hi = __uint_as_float(_uhi); } while (0)
#define FMA2(acc, a, b) \
    asm("fma.rn.f32x2 %0, %1, %2, %0;" : "+l"(acc) : "l"(a), "l"(b))

__device__ __forceinline__ unsigned smem_u32p(const void* p) {
    return (unsigned)__cvta_generic_to_shared(p);
}
#define LDSM_X4(r0, r1, r2, r3, addr) \
    asm volatile("ldmatrix.sync.aligned.m8n8.x4.shared.b16 {%0,%1,%2,%3}, [%4];" \
        : "=r"(r0), "=r"(r1), "=r"(r2), "=r"(r3) : "r"(addr))
#define LDSM_X4T(r0, r1, r2, r3, addr) \
    asm volatile("ldmatrix.sync.aligned.m8n8.x4.trans.shared.b16 {%0,%1,%2,%3}, [%4];" \
        : "=r"(r0), "=r"(r1), "=r"(r2), "=r"(r3) : "r"(addr))
#define MMA16816(c, a0, a1, a2, a3, b0, b1) \
    asm volatile("mma.sync.aligned.m16n8k16.row.col.f32.f16.f16.f32 " \
        "{%0,%1,%2,%3}, {%4,%5,%6,%7}, {%8,%9}, {%0,%1,%2,%3};" \
        : "+f"(c[0]), "+f"(c[1]), "+f"(c[2]), "+f"(c[3]) \
        : "r"(a0), "r"(a1), "r"(a2), "r"(a3), "r"(b0), "r"(b1))

// ---------------- CSR build ------------------------------------------------
__global__ void k_count(const int* __restrict__ dst) {
    int e = blockIdx.x * blockDim.x + threadIdx.x;
    if (e < EE) atomicAdd(&d_deg[dst[e]], 1);
}

__global__ void k_blocksum() {
    __shared__ int sh[1024];
    int i = blockIdx.x * 1024 + threadIdx.x;
    sh[threadIdx.x] = (i < NN) ? d_deg[i] : 0;
    __syncthreads();
    for (int s = 512; s; s >>= 1) {
        if (threadIdx.x < s) sh[threadIdx.x] += sh[threadIdx.x + s];
        __syncthreads();
    }
    if (threadIdx.x == 0) d_bsum[blockIdx.x] = sh[0];
}

__global__ void k_scanbsum(int nb) {
    __shared__ int sh[64];
    int t = threadIdx.x;
    int v = (t < nb) ? d_bsum[t] : 0;
    sh[t] = v;
    __syncthreads();
    for (int o = 1; o < 64; o <<= 1) {
        int u = (t >= o) ? sh[t - o] : 0;
        __syncthreads();
        sh[t] += u;
        __syncthreads();
    }
    if (t < nb) d_bpre[t] = sh[t] - v;
}

__global__ void k_scanfinal() {
    __shared__ int sh[1024];
    int tid = threadIdx.x;
    int i = blockIdx.x * 1024 + tid;
    int v = (i < NN) ? d_deg[i] : 0;
    sh[tid] = v;
    __syncthreads();
    for (int off = 1; off < 1024; off <<= 1) {
        int t = (tid >= off) ? sh[tid - off] : 0;
        __syncthreads();
        sh[tid] += t;
        __syncthreads();
    }
    if (i < NN) d_rowoff[i] = d_bpre[blockIdx.x] + sh[tid] - v;
    if (i == 0) d_rowoff[NN] = EE;
}

__global__ void k_scatter(const int* __restrict__ src, const int* __restrict__ dst) {
    int e = blockIdx.x * blockDim.x + threadIdx.x;
    if (e < EE) {
        int d = dst[e];
        int p = d_rowoff[d] + atomicAdd(&d_cur[d], 1);
        d_srt[p] = src[e];
    }
}

// ---------------- fp32 -> fp16 conversion (x and W_fc) ---------------------
__global__ void k_cvt(const float* __restrict__ x, const float* __restrict__ W_fc) {
    int i = blockIdx.x * blockDim.x + threadIdx.x;
    const int totx = NN * 128 / 4;
    const int totw = 128 * 256 / 4;
    if (i < totx) {
        float4 v = ((const float4*)x)[i];
        __half2* o = (__half2*)d_x_h + i * 2;
        o[0] = __floats2half2_rn(v.x, v.y);
        o[1] = __floats2half2_rn(v.z, v.w);
    } else if (i < totx + totw) {
        int j = i - totx;
        float4 v = ((const float4*)W_fc)[j];
        __half2* o = (__half2*)d_wfc_h + j * 2;
        o[0] = __floats2half2_rn(v.x, v.y);
        o[1] = __floats2half2_rn(v.z, v.w);
    }
}

// ---------------- HMMA feat GEMM: feat = x_h @ wfc_h  (fp16 in, fp32 acc) --
// C [M,256] = A [M,128] x B [128,256].  128x128 tile, 8 warps of 32x64.
__global__ void __launch_bounds__(256, 2)
k_hgemm(const __half* __restrict__ A, const __half* __restrict__ B,
        __half* __restrict__ C, int M) {
    constexpr int BM = 128, BN = 128, BK = 32, KTOT = 128, NC = 256;
    constexpr int ASTR = BK + 8;   // 40 halves = 80B row stride (conflict-free)
    constexpr int BSTR = BN + 8;   // 136 halves = 272B row stride (conflict-free)
    __shared__ __align__(16) __half As[2][BM][ASTR];
    __shared__ __align__(16) __half Bs[2][BK][BSTR];
    int t = threadIdx.x;
    int lane = t & 31, w = t >> 5;
    int wm = w & 3, wn = w >> 2;           // warp tile: rows wm*32, cols wn*64
    int m0 = blockIdx.x * BM, n0 = blockIdx.y * BN;

    float acc[2][8][4] = {};
    uint4 aReg[2], bReg[2];

    // prologue: slab 0 -> regs
#pragma unroll
    for (int l = 0; l < 2; l++) {
        int idx = t + l * 256;
        int row = idx >> 2, kc = (idx & 3) * 8;
        uint4 v = make_uint4(0, 0, 0, 0);
        if (m0 + row < M) v = *(const uint4*)(A + (size_t)(m0 + row) * KTOT + kc);
        aReg[l] = v;
        int brow = idx >> 4, bn = (idx & 15) * 8;
        bReg[l] = *(const uint4*)(B + (size_t)brow * NC + n0 + bn);
    }

    int s = 0;
    for (int it = 0; it < KTOT / BK; it++) {
#pragma unroll
        for (int l = 0; l < 2; l++) {
            int idx = t + l * 256;
            int row = idx >> 2, kc = (idx & 3) * 8;
            *(uint4*)&As[s][row][kc] = aReg[l];
            int brow = idx >> 4, bn = (idx & 15) * 8;
            *(uint4*)&Bs[s][brow][bn] = bReg[l];
        }
        __syncthreads();

        if (it + 1 < KTOT / BK) {
            int k0 = (it + 1) * BK;
#pragma unroll
            for (int l = 0; l < 2; l++) {
                int idx = t + l * 256;
                int row = idx >> 2, kc = (idx & 3) * 8;
                uint4 v = make_uint4(0, 0, 0, 0);
                if (m0 + row < M) v = *(const uint4*)(A + (size_t)(m0 + row) * KTOT + k0 + kc);
                aReg[l] = v;
                int brow = idx >> 4, bn = (idx & 15) * 8;
                bReg[l] = *(const uint4*)(B + (size_t)(k0 + brow) * NC + n0 + bn);
            }
        }

        int g = lane >> 3;            // ldmatrix thread-group 0..3
        int lr = lane & 7;
#pragma unroll
        for (int ks = 0; ks < BK; ks += 16) {
            unsigned af[2][4];
#pragma unroll
            for (int m = 0; m < 2; m++) {
                int row = wm * 32 + m * 16 + (g & 1) * 8 + lr;
                int col = ks + (g >> 1) * 8;
                LDSM_X4(af[m][0], af[m][1], af[m][2], af[m][3],
                        smem_u32p(&As[s][row][col]));
            }
            unsigned bf[4][4];
#pragma unroll
            for (int j = 0; j < 4; j++) {
                int krow = ks + (g & 1) * 8 + lr;
                int col = wn * 64 + j * 16 + (g >> 1) * 8;
                LDSM_X4T(bf[j][0], bf[j][1], bf[j][2], bf[j][3],
                         smem_u32p(&Bs[s][krow][col]));
            }
#pragma unroll
            for (int m = 0; m < 2; m++)
#pragma unroll
                for (int jn = 0; jn < 8; jn++) {
                    int j = jn >> 1, h = jn & 1;
                    MMA16816(acc[m][jn], af[m][0], af[m][1], af[m][2], af[m][3],
                             bf[j][h * 2], bf[j][h * 2 + 1]);
                }
        }
        __syncthreads();
        s ^= 1;
    }

    // epilogue: fp32 acc -> fp16 C
    int qr = lane >> 2, qc = (lane & 3) * 2;
#pragma unroll
    for (int m = 0; m < 2; m++) {
        int rlo = m0 + wm * 32 + m * 16 + qr;
        int rhi = rlo + 8;
#pragma unroll
        for (int jn = 0; jn < 8; jn++) {
            int col = n0 + wn * 64 + jn * 8 + qc;
            if (rlo < M)
                *(__half2*)(C + (size_t)rlo * NC + col) = __floats2half2_rn(acc[m][jn][0], acc[m][jn][1]);
            if (rhi < M)
                *(__half2*)(C + (size_t)rhi * NC + col) = __floats2half2_rn(acc[m][jn][2], acc[m][jn][3]);
        }
    }
}

// ---------------- fp32 GEMM (FFMA2, double buffer) for z / merge -----------
template<int BM, int BN, int TM, int TN, int MINB, bool HALF_OUT>
__global__ void __launch_bounds__((BM / TM) * (BN / TN), MINB)
k_gemm(const float* __restrict__ A1, int K1,
       const float* __restrict__ A2, int K2,
       const float* __restrict__ B,
       const float* __restrict__ bias,
       void* __restrict__ Cv, int M, int Ncols) {
    constexpr int BK = 16;
    constexpr int NTH = (BM / TM) * (BN / TN);
    constexpr int AL = BM * BK / 4 / NTH;
    constexpr int BL = BK * BN / 4 / NTH;
    __shared__ __align__(16) float As[2][BK][BM + 4];
    __shared__ __align__(16) float Bs[2][BK][BN + 4];
    int t = threadIdx.x;
    int tx = t % (BN / TN);
    int ty = t / (BN / TN);
    int m0 = blockIdx.x * BM, n0 = blockIdx.y * BN;
    int K = K1 + K2;
    int nIter = K / BK;
    unsigned long long acc2[TM][TN / 2] = {};

    float4 aReg[AL], bReg[BL];

#pragma unroll
    for (int l = 0; l < AL; l++) {
        int fidx = t + l * NTH;
        int row = fidx / (BK / 4);
        int c4  = (fidx % (BK / 4)) * 4;
        int gm = m0 + row;
        float4 av = make_float4(0.f, 0.f, 0.f, 0.f);
        if (gm < M) {
            if (c4 < K1) av = *(const float4*)(A1 + (size_t)gm * K1 + c4);
            else         av = *(const float4*)(A2 + (size_t)gm * K2 + (c4 - K1));
        }
        aReg[l] = av;
    }
#pragma unroll
    for (int l = 0; l < BL; l++) {
        int fidx = t + l * NTH;
        int brow = fidx / (BN / 4);
        int bc4  = (fidx % (BN / 4)) * 4;
        bReg[l] = *(const float4*)(B + (size_t)brow * Ncols + n0 + bc4);
    }

    int s = 0;
    for (int it = 0; it < nIter; it++) {
#pragma unroll
        for (int l = 0; l < AL; l++) {
            int fidx = t + l * NTH;
            int row = fidx / (BK / 4);
            int c4  = (fidx % (BK / 4)) * 4;
            As[s][c4 + 0][row] = aReg[l].x;
            As[s][c4 + 1][row] = aReg[l].y;
            As[s][c4 + 2][row] = aReg[l].z;
            As[s][c4 + 3][row] = aReg[l].w;
        }
#pragma unroll
        for (int l = 0; l < BL; l++) {
            int fidx = t + l * NTH;
            int brow = fidx / (BN / 4);
            int bc4  = (fidx % (BN / 4)) * 4;
            *(float4*)&Bs[s][brow][bc4] = bReg[l];
        }
        __syncthreads();

        if (it + 1 < nIter) {
            int k0 = (it + 1) * BK;
#pragma unroll
            for (int l = 0; l < AL; l++) {
                int fidx = t + l * NTH;
                int row = fidx / (BK / 4);
                int c4  = (fidx % (BK / 4)) * 4;
                int gm = m0 + row;
                int k = k0 + c4;
                float4 av = make_float4(0.f, 0.f, 0.f, 0.f);
                if (gm < M) {
                    if (k < K1) av = *(const float4*)(A1 + (size_t)gm * K1 + k);
                    else        av = *(const float4*)(A2 + (size_t)gm * K2 + (k - K1));
                }
                aReg[l] = av;
            }
#pragma unroll
            for (int l = 0; l < BL; l++) {
                int fidx = t + l * NTH;
                int brow = fidx / (BN / 4);
                int bc4  = (fidx % (BN / 4)) * 4;
                bReg[l] = *(const float4*)(B + (size_t)(k0 + brow) * Ncols + n0 + bc4);
            }
        }

#pragma unroll
        for (int kk = 0; kk < BK; kk++) {
            float af[TM], bf[TN];
#pragma unroll
            for (int i = 0; i < TM; i += 4)
                *(float4*)&af[i] = *(const float4*)&As[s][kk][ty * TM + i];
#pragma unroll
            for (int j = 0; j < TN; j += 4)
                *(float4*)&bf[j] = *(const float4*)&Bs[s][kk][tx * TN + j];
            unsigned long long bb[TN / 2];
#pragma unroll
            for (int j = 0; j < TN / 2; j++) PACK2(bb[j], bf[2 * j], bf[2 * j + 1]);
#pragma unroll
            for (int i = 0; i < TM; i++) {
                unsigned long long aa;
                PACK2(aa, af[i], af[i]);
#pragma unroll
                for (int j = 0; j < TN / 2; j++) FMA2(acc2[i][j], aa, bb[j]);
            }
        }
        s ^= 1;
    }

#pragma unroll
    for (int i = 0; i < TM; i++) {
        int gm = m0 + ty * TM + i;
        if (gm < M) {
#pragma unroll
            for (int j = 0; j < TN; j += 4) {
                int gn = n0 + tx * TN + j;
                float4 v;
                UNPACK2(v.x, v.y, acc2[i][j / 2]);
                UNPACK2(v.z, v.w, acc2[i][j / 2 + 1]);
                if (bias) {
                    v.x += bias[gn + 0]; v.y += bias[gn + 1];
                    v.z += bias[gn + 2]; v.w += bias[gn + 3];
                }
                if (HALF_OUT) {
                    __half2 h0 = __floats2half2_rn(v.x, v.y);
                    __half2 h1 = __floats2half2_rn(v.z, v.w);
                    __half2* cp = (__half2*)((__half*)Cv + (size_t)gm * Ncols + gn);
                    cp[0] = h0; cp[1] = h1;
                } else {
                    *(float4*)((float*)Cv + (size_t)gm * Ncols + gn) = v;
                }
            }
        }
    }
}

// ---------------- per-node prep: el/er dots + gate pre-projection ----------
__global__ void k_node(const float* __restrict__ x,
                       const float* __restrict__ attn_l,
                       const float* __restrict__ attn_r,
                       const float* __restrict__ W_gate) {
    int w = (blockIdx.x * blockDim.x + threadIdx.x) >> 5;
    if (w >= NN) return;
    int lane = threadIdx.x & 31;

    uint4 u = *(const uint4*)(d_feat_h + (size_t)w * 256 + lane * 8);
    float f[8];
    {
        float2 v0 = __half22float2(*(__half2*)&u.x);
        float2 v1 = __half22float2(*(__half2*)&u.y);
        float2 v2 = __half22float2(*(__half2*)&u.z);
        float2 v3 = __half22float2(*(__half2*)&u.w);
        f[0] = v0.x; f[1] = v0.y; f[2] = v1.x; f[3] = v1.y;
        f[4] = v2.x; f[5] = v2.y; f[6] = v3.x; f[7] = v3.y;
    }
    const float4* al = (const float4*)(attn_l + lane * 8);
    const float4* ar = (const float4*)(attn_r + lane * 8);
    float4 a0 = al[0], a1 = al[1];
    float4 r0 = ar[0], r1 = ar[1];
    float sl = f[0] * a0.x + f[1] * a0.y + f[2] * a0.z + f[3] * a0.w
             + f[4] * a1.x + f[5] * a1.y + f[6] * a1.z + f[7] * a1.w;
    float sr = f[0] * r0.x + f[1] * r0.y + f[2] * r0.z + f[3] * r0.w
             + f[4] * r1.x + f[5] * r1.y + f[6] * r1.z + f[7] * r1.w;
#pragma unroll
    for (int o = 1; o < 8; o <<= 1) {
        sl += __shfl_xor_sync(0xffffffffu, sl, o);
        sr += __shfl_xor_sync(0xffffffffu, sr, o);
    }
    if ((lane & 7) == 0) {
        d_el[w * 4 + (lane >> 3)] = sl;
        d_er[w * 4 + (lane >> 3)] = sr;
    }

    float4 xv = *(const float4*)(x + (size_t)w * 128 + lane * 4);
    const float4* Wg4 = (const float4*)W_gate;
    float s0 = 0, s1 = 0, s2 = 0, s3 = 0;
    float q0 = 0, q1 = 0, q2 = 0, q3 = 0;
    float xa[4] = { xv.x, xv.y, xv.z, xv.w };
#pragma unroll
    for (int i = 0; i < 4; i++) {
        float4 ws = __ldg(&Wg4[lane * 4 + i]);
        float4 wm = __ldg(&Wg4[192 + lane * 4 + i]);
        s0 += xa[i] * ws.x; s1 += xa[i] * ws.y; s2 += xa[i] * ws.z; s3 += xa[i] * ws.w;
        q0 += xa[i] * wm.x; q1 += xa[i] * wm.y; q2 += xa[i] * wm.z; q3 += xa[i] * wm.w;
    }
#pragma unroll
    for (int o = 16; o; o >>= 1) {
        s0 += __shfl_xor_sync(0xffffffffu, s0, o);
        s1 += __shfl_xor_sync(0xffffffffu, s1, o);
        s2 += __shfl_xor_sync(0xffffffffu, s2, o);
        s3 += __shfl_xor_sync(0xffffffffu, s3, o);
        q0 += __shfl_xor_sync(0xffffffffu, q0, o);
        q1 += __shfl_xor_sync(0xffffffffu, q1, o);
        q2 += __shfl_xor_sync(0xffffffffu, q2, o);
        q3 += __shfl_xor_sync(0xffffffffu, q3, o);
    }
    if (lane == 0) {
        *(float4*)(d_gs  + w * 4) = make_float4(s0, s1, s2, s3);
        *(float4*)(d_gmn + w * 4) = make_float4(q0, q1, q2, q3);
    }
}

// ---------------- fused single-pass aggregation, 2-way unrolled, fp16 reads -
__global__ void k_agg(const float* __restrict__ W_gate,
                      const float* __restrict__ b_gate,
                      const float* __restrict__ b_gat) {
    int w = (blockIdx.x * blockDim.x + threadIdx.x) >> 5;
    if (w >= NN) return;
    int lane = threadIdx.x & 31;
    int h = lane >> 3;
    int beg = d_rowoff[w], end = d_rowoff[w + 1];
    float erh = __ldg(d_er + w * 4 + h);

    float mz0 = -FLT_MAX, mz1 = -FLT_MAX;
    float sg0 = 0, sg1 = 0, sg2 = 0, sg3 = 0;

    float mA = -FLT_MAX, dA = 0.f;
    float A0 = 0, A1 = 0, A2 = 0, A3 = 0, A4 = 0, A5 = 0, A6 = 0, A7 = 0;
    float mB = -FLT_MAX, dB = 0.f;
    float B0 = 0, B1 = 0, B2 = 0, B3 = 0, B4 = 0, B5 = 0, B6 = 0, B7 = 0;

    int p = beg;
    for (; p + 1 < end; p += 2) {
        int sa = __ldg(d_srt + p);
        int sb = __ldg(d_srt + p + 1);

        __half2 zha = *(const __half2*)(d_z_h + (size_t)sa * 64 + lane * 2);
        __half2 zhb = *(const __half2*)(d_z_h + (size_t)sb * 64 + lane * 2);
        float2 za = __half22float2(zha);
        float2 zb = __half22float2(zhb);
        float4 ga = __ldg((const float4*)(d_gmn + sa * 4));
        float4 gb = __ldg((const float4*)(d_gmn + sb * 4));
        float ea_ = __ldg(d_el + sa * 4 + h);
        float eb_ = __ldg(d_el + sb * 4 + h);
        uint4 ua = *(const uint4*)(d_feat_h + (size_t)sa * 256 + lane * 8);
        uint4 ub = *(const uint4*)(d_feat_h + (size_t)sb * 256 + lane * 8);
        float2 fa0 = __half22float2(*(__half2*)&ua.x);
        float2 fa1 = __half22float2(*(__half2*)&ua.y);
        float2 fa2 = __half22float2(*(__half2*)&ua.z);
        float2 fa3 = __half22float2(*(__half2*)&ua.w);
        float2 fb0 = __half22float2(*(__half2*)&ub.x);
        float2 fb1 = __half22float2(*(__half2*)&ub.y);
        float2 fb2 = __half22float2(*(__half2*)&ub.z);
        float2 fb3 = __half22float2(*(__half2*)&ub.w);

        mz0 = fmaxf(mz0, fmaxf(za.x, zb.x));
        mz1 = fmaxf(mz1, fmaxf(za.y, zb.y));
        sg0 += ga.x + gb.x; sg1 += ga.y + gb.y;
        sg2 += ga.z + gb.z; sg3 += ga.w + gb.w;

        float eA = lrelu(ea_ + erh);
        float mnA = fmaxf(mA, eA);
        float cA = __expf(mA - mnA);
        float wA = __expf(eA - mnA);
        mA = mnA;
        dA = dA * cA + wA;
        A0 = A0 * cA + wA * fa0.x; A1 = A1 * cA + wA * fa0.y;
        A2 = A2 * cA + wA * fa1.x; A3 = A3 * cA + wA * fa1.y;
        A4 = A4 * cA + wA * fa2.x; A5 = A5 * cA + wA * fa2.y;
        A6 = A6 * cA + wA * fa3.x; A7 = A7 * cA + wA * fa3.y;

        float eB = lrelu(eb_ + erh);
        float mnB = fmaxf(mB, eB);
        float cB = __expf(mB - mnB);
        float wB = __expf(eB - mnB);
        mB = mnB;
        dB = dB * cB + wB;
        B0 = B0 * cB + wB * fb0.x; B1 = B1 * cB + wB * fb0.y;
        B2 = B2 * cB + wB * fb1.x; B3 = B3 * cB + wB * fb1.y;
        B4 = B4 * cB + wB * fb2.x; B5 = B5 * cB + wB * fb2.y;
        B6 = B6 * cB + wB * fb3.x; B7 = B7 * cB + wB * fb3.y;
    }
    if (p < end) {
        int sa = __ldg(d_srt + p);
        __half2 zha = *(const __half2*)(d_z_h + (size_t)sa * 64 + lane * 2);
        float2 za = __half22float2(zha);
        float4 ga = __ldg((const float4*)(d_gmn + sa * 4));
        float ea_ = __ldg(d_el + sa * 4 + h);
        uint4 ua = *(const uint4*)(d_feat_h + (size_t)sa * 256 + lane * 8);
        float2 fa0 = __half22float2(*(__half2*)&ua.x);
        float2 fa1 = __half22float2(*(__half2*)&ua.y);
        float2 fa2 = __half22float2(*(__half2*)&ua.z);
        float2 fa3 = __half22float2(*(__half2*)&ua.w);
        mz0 = fmaxf(mz0, za.x); mz1 = fmaxf(mz1, za.y);
        sg0 += ga.x; sg1 += ga.y; sg2 += ga.z; sg3 += ga.w;
        float eA = lrelu(ea_ + erh);
        float mnA = fmaxf(mA, eA);
        float cA = __expf(mA - mnA);
        float wA = __expf(eA - mnA);
        mA = mnA;
        dA = dA * cA + wA;
        A0 = A0 * cA + wA * fa0.x; A1 = A1 * cA + wA * fa0.y;
        A2 = A2 * cA + wA * fa1.x; A3 = A3 * cA + wA * fa1.y;
        A4 = A4 * cA + wA * fa2.x; A5 = A5 * cA + wA * fa2.y;
        A6 = A6 * cA + wA * fa3.x; A7 = A7 * cA + wA * fa3.y;
    }

    float mh = fmaxf(mA, mB);
    float cA = (dA > 0.f) ? __expf(mA - mh) : 0.f;
    float cB = (dB > 0.f) ? __expf(mB - mh) : 0.f;
    float dh = dA * cA + dB * cB;
    float accs[8];
    accs[0] = A0 * cA + B0 * cB; accs[1] = A1 * cA + B1 * cB;
    accs[2] = A2 * cA + B2 * cB; accs[3] = A3 * cA + B3 * cB;
    accs[4] = A4 * cA + B4 * cB; accs[5] = A5 * cA + B5 * cB;
    accs[6] = A6 * cA + B6 * cB; accs[7] = A7 * cA + B7 * cB;

    int deg = end - beg;
    if (deg == 0) { mz0 = 0.f; mz1 = 0.f; }
    float invm = 1.f / (float)(deg > 1 ? deg : 1);

    const float4* Wg4 = (const float4*)W_gate;
    float4 wz0 = __ldg(&Wg4[128 + 2 * lane]);
    float4 wz1 = __ldg(&Wg4[129 + 2 * lane]);
    float t0 = mz0 * wz0.x + mz1 * wz1.x;
    float t1 = mz0 * wz0.y + mz1 * wz1.y;
    float t2 = mz0 * wz0.z + mz1 * wz1.z;
    float t3 = mz0 * wz0.w + mz1 * wz1.w;
#pragma unroll
    for (int o = 16; o; o >>= 1) {
        t0 += __shfl_xor_sync(0xffffffffu, t0, o);
        t1 += __shfl_xor_sync(0xffffffffu, t1, o);
        t2 += __shfl_xor_sync(0xffffffffu, t2, o);
        t3 += __shfl_xor_sync(0xffffffffu, t3, o);
    }
    float4 gsv = *(const float4*)(d_gs + w * 4);
    float4 bg  = *(const float4*)b_gate;
    t0 += gsv.x + sg0 * invm + bg.x;
    t1 += gsv.y + sg1 * invm + bg.y;
    t2 += gsv.z + sg2 * invm + bg.z;
    t3 += gsv.w + sg3 * invm + bg.w;
    float g0 = 1.f / (1.f + __expf(-t0));
    float g1 = 1.f / (1.f + __expf(-t1));
    float g2 = 1.f / (1.f + __expf(-t2));
    float g3 = 1.f / (1.f + __expf(-t3));
    float gh = h == 0 ? g0 : (h == 1 ? g1 : (h == 2 ? g2 : g3));

    float invd = dh > 0.f ? 1.f / dh : 0.f;
#pragma unroll
    for (int i = 0; i < 8; i++) {
        float ao = accs[i] * invd + __ldg(b_gat + lane * 8 + i);
        float c = gh * ao;
        c += __shfl_xor_sync(0xffffffffu, c, 8);
        c += __shfl_xor_sync(0xffffffffu, c, 16);
        if (lane < 8) d_gated[(size_t)w * 64 + lane * 8 + i] = 0.25f * c;
    }
}

// ---------------- launch ----------------------------------------------------
extern "C" void kernel_launch(void* const* d_in, const int* in_sizes, int n_in,
                              void* d_out, int out_size) {
    const float* x       = (const float*)d_in[0];
    const int*   ei      = (const int*)d_in[1];
    const float* W_gm    = (const float*)d_in[2];
    const float* b_gm    = (const float*)d_in[3];
    const float* W_gate  = (const float*)d_in[4];
    const float* b_gate  = (const float*)d_in[5];
    const float* W_fc    = (const float*)d_in[6];
    const float* attn_l  = (const float*)d_in[7];
    const float* attn_r  = (const float*)d_in[8];
    const float* b_gat   = (const float*)d_in[9];
    const float* W_merge = (const float*)d_in[10];
    const float* b_merge = (const float*)d_in[11];
    float* out = (float*)d_out;

    const int* src = ei;
    const int* dst = ei + EE;

    void *feat_h, *z_h, *x_h, *wfc_h;
    float *gated;
    int *degp, *curp;
    cudaGetSymbolAddress(&feat_h, d_feat_h);
    cudaGetSymbolAddress(&z_h,    d_z_h);
    cudaGetSymbolAddress(&x_h,    d_x_h);
    cudaGetSymbolAddress(&wfc_h,  d_wfc_h);
    cudaGetSymbolAddress((void**)&gated, d_gated);
    cudaGetSymbolAddress((void**)&degp,  d_deg);
    cudaGetSymbolAddress((void**)&curp,  d_cur);

    const int NB = (NN + 1023) / 1024;  // 49
    int warp_blocks = (NN * 32 + 255) / 256;
    int cvt_tot = NN * 128 / 4 + 128 * 256 / 4;

    cudaMemsetAsync(degp, 0, NN * sizeof(int));
    cudaMemsetAsync(curp, 0, NN * sizeof(int));
    k_count<<<(EE + 255) / 256, 256>>>(dst);
    k_blocksum<<<NB, 1024>>>();
    k_cvt<<<(cvt_tot + 255) / 256, 256>>>(x, W_fc);

    // launch 6 — captured by ncu: HMMA feat GEMM
    dim3 gfeat((NN + 127) / 128, 2);
    k_hgemm<<<gfeat, 256>>>((const __half*)x_h, (const __half*)wfc_h,
                            (__half*)feat_h, NN);

    k_scanbsum<<<1, 64>>>(NB);
    k_scanfinal<<<NB, 1024>>>();
    k_scatter<<<(EE + 255) / 256, 256>>>(src, dst);

    dim3 gz((NN + 127) / 128, 1);
    k_gemm<128, 64, 8, 8, 4, true><<<gz, 128>>>(x, 128, nullptr, 0, W_gm, b_gm, z_h, NN, 64);

    k_node<<<warp_blocks, 256>>>(x, attn_l, attn_r, W_gate);
    k_agg<<<warp_blocks, 256>>>(W_gate, b_gate, b_gat);

    dim3 gm((NN + 127) / 128, 1);
    k_gemm<128, 64, 8, 8, 4, false><<<gm, 128>>>(x, 128, gated, 64, W_merge, b_merge, out, NN, 64);
}